// round 3
// baseline (speedup 1.0000x reference)
#include <cuda_runtime.h>
#include <math_constants.h>

// Problem constants (Unidir_atten: B=16, L1=L2=1024, H=768)
#define BSZ 16
#define L1D 1024
#define L2D 1024
#define HD  768

// Scratch (device globals: no allocations allowed)
__device__ float g_xp[(size_t)BSZ * L1D * HD];        // relu(x1 @ W^T + b)   50 MB
__device__ float g_yp[(size_t)BSZ * L2D * HD];        // relu(x2 @ W^T + b)   50 MB
__device__ float g_sc[(size_t)BSZ * L1D * L2D];       // scores / probs       64 MB
__device__ float g_maskbias[BSZ * L2D];               // 0 or -1e30 per (b,j)
__device__ int   g_mask_is_i32;

#define NEG_BIG (-1e30f)

// ---------------------------------------------------------------------------
// Mask dtype detection: jax bool may arrive as int8 or int32. If int32 (values
// 0/1 little-endian), every byte at index %4 != 0 is zero. Scan first
// BSZ*L2D bytes (safe under both interpretations).
// ---------------------------------------------------------------------------
__global__ void detect_mask_kernel(const unsigned char* __restrict__ m) {
    __shared__ int bad;
    if (threadIdx.x == 0) bad = 0;
    __syncthreads();
    for (int i = threadIdx.x; i < BSZ * L2D; i += blockDim.x) {
        if ((i & 3) && m[i]) bad = 1;
    }
    __syncthreads();
    if (threadIdx.x == 0) g_mask_is_i32 = bad ? 0 : 1;
}

__global__ void maskbias_kernel(const void* __restrict__ m) {
    int i = blockIdx.x * blockDim.x + threadIdx.x;
    if (i >= BSZ * L2D) return;
    bool masked;
    if (g_mask_is_i32) masked = ((const int*)m)[i] != 0;
    else               masked = ((const unsigned char*)m)[i] != 0;
    g_maskbias[i] = masked ? NEG_BIG : 0.0f;
}

// ---------------------------------------------------------------------------
// Tiled GEMM config: 64x64 tile, K-step 16, 256 threads, 4x4 per thread.
// ---------------------------------------------------------------------------
#define TBM 64
#define TBN 64
#define TBK 16

// proj: C[m,n] = relu(sum_k A[m,k] * W[n,k] + bias[n])
// A: M x HD row-major (M = BSZ*L1D), W: HD x HD row-major. which: 0 -> g_xp, 1 -> g_yp
__global__ __launch_bounds__(256) void proj_kernel(
    const float* __restrict__ A, const float* __restrict__ W,
    const float* __restrict__ bias, int which)
{
    __shared__ float As[TBK][TBM];
    __shared__ float Bs[TBK][TBN];
    float* C = which ? g_yp : g_xp;

    const int tid = threadIdx.x;
    const int m0 = blockIdx.x * TBM;
    const int n0 = blockIdx.y * TBN;
    const int ty = tid / 16, tx = tid % 16;
    const int lr = tid >> 2;            // 0..63
    const int lc = (tid & 3) * 4;       // 0,4,8,12

    const float* Ap = A + (size_t)(m0 + lr) * HD;
    const float* Wp = W + (size_t)(n0 + lr) * HD;

    float acc[4][4] = {};

    for (int k0 = 0; k0 < HD; k0 += TBK) {
        float4 av = *(const float4*)(Ap + k0 + lc);
        float4 wv = *(const float4*)(Wp + k0 + lc);
        As[lc + 0][lr] = av.x; As[lc + 1][lr] = av.y;
        As[lc + 2][lr] = av.z; As[lc + 3][lr] = av.w;
        Bs[lc + 0][lr] = wv.x; Bs[lc + 1][lr] = wv.y;
        Bs[lc + 2][lr] = wv.z; Bs[lc + 3][lr] = wv.w;
        __syncthreads();
        #pragma unroll
        for (int k = 0; k < TBK; k++) {
            float4 a = *(const float4*)&As[k][ty * 4];
            float4 b = *(const float4*)&Bs[k][tx * 4];
            float ar[4] = {a.x, a.y, a.z, a.w};
            float br[4] = {b.x, b.y, b.z, b.w};
            #pragma unroll
            for (int i = 0; i < 4; i++)
                #pragma unroll
                for (int j = 0; j < 4; j++)
                    acc[i][j] += ar[i] * br[j];
        }
        __syncthreads();
    }

    #pragma unroll
    for (int i = 0; i < 4; i++) {
        int m = m0 + ty * 4 + i;
        #pragma unroll
        for (int j = 0; j < 4; j++) {
            int n = n0 + tx * 4 + j;
            float v = acc[i][j] + bias[n];
            C[(size_t)m * HD + n] = v > 0.f ? v : 0.f;
        }
    }
}

// scores: S[b,i,j] = dot(xp[b,i,:], yp[b,j,:]) + maskbias[b,j]   (NT GEMM per batch)
__global__ __launch_bounds__(256) void scores_kernel()
{
    __shared__ float As[TBK][TBM];
    __shared__ float Bs[TBK][TBN];
    const int b = blockIdx.z;
    const float* A  = g_xp + (size_t)b * L1D * HD;
    const float* Bm = g_yp + (size_t)b * L2D * HD;
    float* C = g_sc + (size_t)b * L1D * L2D;

    const int tid = threadIdx.x;
    const int m0 = blockIdx.x * TBM;
    const int n0 = blockIdx.y * TBN;
    const int ty = tid / 16, tx = tid % 16;
    const int lr = tid >> 2;
    const int lc = (tid & 3) * 4;

    const float* Ap = A  + (size_t)(m0 + lr) * HD;
    const float* Bp = Bm + (size_t)(n0 + lr) * HD;

    float acc[4][4] = {};

    for (int k0 = 0; k0 < HD; k0 += TBK) {
        float4 av = *(const float4*)(Ap + k0 + lc);
        float4 bv = *(const float4*)(Bp + k0 + lc);
        As[lc + 0][lr] = av.x; As[lc + 1][lr] = av.y;
        As[lc + 2][lr] = av.z; As[lc + 3][lr] = av.w;
        Bs[lc + 0][lr] = bv.x; Bs[lc + 1][lr] = bv.y;
        Bs[lc + 2][lr] = bv.z; Bs[lc + 3][lr] = bv.w;
        __syncthreads();
        #pragma unroll
        for (int k = 0; k < TBK; k++) {
            float4 a = *(const float4*)&As[k][ty * 4];
            float4 bb = *(const float4*)&Bs[k][tx * 4];
            float ar[4] = {a.x, a.y, a.z, a.w};
            float br[4] = {bb.x, bb.y, bb.z, bb.w};
            #pragma unroll
            for (int i = 0; i < 4; i++)
                #pragma unroll
                for (int j = 0; j < 4; j++)
                    acc[i][j] += ar[i] * br[j];
        }
        __syncthreads();
    }

    #pragma unroll
    for (int i = 0; i < 4; i++) {
        int m = m0 + ty * 4 + i;
        #pragma unroll
        for (int j = 0; j < 4; j++) {
            int n = n0 + tx * 4 + j;
            C[(size_t)m * L2D + n] = acc[i][j] + g_maskbias[b * L2D + n];
        }
    }
}

// softmax over last dim of g_sc, in place. One block (256 thr) per row of 1024.
__global__ __launch_bounds__(256) void softmax_kernel()
{
    const int row = blockIdx.x;
    float* p = g_sc + (size_t)row * L2D;
    const int t = threadIdx.x;
    __shared__ float red[8];

    float v[4];
    float mx = NEG_BIG;
    #pragma unroll
    for (int u = 0; u < 4; u++) {
        v[u] = p[t + u * 256];
        mx = fmaxf(mx, v[u]);
    }
    #pragma unroll
    for (int o = 16; o > 0; o >>= 1)
        mx = fmaxf(mx, __shfl_xor_sync(0xffffffffu, mx, o));
    if ((t & 31) == 0) red[t >> 5] = mx;
    __syncthreads();
    if (t == 0) {
        float m = red[0];
        #pragma unroll
        for (int i = 1; i < 8; i++) m = fmaxf(m, red[i]);
        red[0] = m;
    }
    __syncthreads();
    mx = red[0];
    __syncthreads();

    float s = 0.f;
    #pragma unroll
    for (int u = 0; u < 4; u++) {
        v[u] = __expf(v[u] - mx);   // finite - finite: never NaN
        s += v[u];
    }
    #pragma unroll
    for (int o = 16; o > 0; o >>= 1)
        s += __shfl_xor_sync(0xffffffffu, s, o);
    if ((t & 31) == 0) red[t >> 5] = s;
    __syncthreads();
    if (t == 0) {
        float m = 0.f;
        #pragma unroll
        for (int i = 0; i < 8; i++) m += red[i];
        red[0] = m;
    }
    __syncthreads();
    float inv = 1.0f / red[0];
    #pragma unroll
    for (int u = 0; u < 4; u++)
        p[t + u * 256] = v[u] * inv;
}

// att[b,i,h] = sum_j P[b,i,j] * x2[b,j,h]  (NN GEMM per batch) + concat epilogue:
// out[b,i] = [x1 | att | x1*att | x1-att]
__global__ __launch_bounds__(256) void attn_concat_kernel(
    const float* __restrict__ X2, const float* __restrict__ X1,
    float* __restrict__ Out)
{
    __shared__ float As[TBK][TBM];
    __shared__ float Bs[TBK][TBN];
    const int b = blockIdx.z;
    const float* A  = g_sc + (size_t)b * L1D * L2D;       // P: L1 x L2 row-major
    const float* Bm = X2 + (size_t)b * L2D * HD;          // X2: L2 x H row-major

    const int tid = threadIdx.x;
    const int m0 = blockIdx.x * TBM;
    const int n0 = blockIdx.y * TBN;
    const int ty = tid / 16, tx = tid % 16;
    const int lr = tid >> 2;           // A-load: 64 rows x 16 k
    const int lc = (tid & 3) * 4;
    const int brr = tid >> 4;          // B-load: 16 k-rows x 64 cols
    const int bcc = (tid & 15) * 4;

    const float* Ap = A + (size_t)(m0 + lr) * L2D;

    float acc[4][4] = {};

    for (int k0 = 0; k0 < L2D; k0 += TBK) {
        float4 av = *(const float4*)(Ap + k0 + lc);
        As[lc + 0][lr] = av.x; As[lc + 1][lr] = av.y;
        As[lc + 2][lr] = av.z; As[lc + 3][lr] = av.w;
        float4 bv = *(const float4*)(Bm + (size_t)(k0 + brr) * HD + n0 + bcc);
        *(float4*)&Bs[brr][bcc] = bv;
        __syncthreads();
        #pragma unroll
        for (int k = 0; k < TBK; k++) {
            float4 a = *(const float4*)&As[k][ty * 4];
            float4 bb = *(const float4*)&Bs[k][tx * 4];
            float ar[4] = {a.x, a.y, a.z, a.w};
            float br[4] = {bb.x, bb.y, bb.z, bb.w};
            #pragma unroll
            for (int i = 0; i < 4; i++)
                #pragma unroll
                for (int j = 0; j < 4; j++)
                    acc[i][j] += ar[i] * br[j];
        }
        __syncthreads();
    }

    #pragma unroll
    for (int i = 0; i < 4; i++) {
        int m = m0 + ty * 4 + i;
        size_t ob = ((size_t)b * L1D + m) * (size_t)(4 * HD);
        const float* x1row = X1 + ((size_t)b * L1D + m) * HD;
        #pragma unroll
        for (int j = 0; j < 4; j++) {
            int n = n0 + tx * 4 + j;
            float a = acc[i][j];
            float xv = x1row[n];
            Out[ob + n]          = xv;
            Out[ob + HD + n]     = a;
            Out[ob + 2 * HD + n] = xv * a;
            Out[ob + 3 * HD + n] = xv - a;
        }
    }
}

// ---------------------------------------------------------------------------
extern "C" void kernel_launch(void* const* d_in, const int* in_sizes, int n_in,
                              void* d_out, int out_size)
{
    const float* x1      = (const float*)d_in[0];
    const float* x2      = (const float*)d_in[1];
    // d_in[2] = x1_mask (unused by the reference)
    const void*  x2_mask = d_in[3];
    const float* W       = (const float*)d_in[4];
    const float* bias    = (const float*)d_in[5];
    float* out = (float*)d_out;
    (void)in_sizes; (void)n_in; (void)out_size;

    detect_mask_kernel<<<1, 256>>>((const unsigned char*)x2_mask);
    maskbias_kernel<<<(BSZ * L2D + 255) / 256, 256>>>(x2_mask);

    dim3 pgrid((BSZ * L1D) / TBM, HD / TBN);          // 256 x 12
    proj_kernel<<<pgrid, 256>>>(x1, W, bias, 0);
    proj_kernel<<<pgrid, 256>>>(x2, W, bias, 1);

    dim3 sgrid(L1D / TBM, L2D / TBN, BSZ);            // 16 x 16 x 16
    scores_kernel<<<sgrid, 256>>>();

    softmax_kernel<<<BSZ * L1D, 256>>>();

    dim3 agrid(L1D / TBM, HD / TBN, BSZ);             // 16 x 12 x 16
    attn_concat_kernel<<<agrid, 256>>>(x2, x1, out);
}

// round 6
// speedup vs baseline: 1.8489x; 1.8489x over previous
#include <cuda_runtime.h>
#include <cuda_bf16.h>
#include <cstdint>

// Problem constants (Unidir_atten: B=16, L1=L2=1024, H=768)
#define BSZ 16
#define L1D 1024
#define L2D 1024
#define HD  768
#define MROWS (2 * BSZ * L1D)          // x1 rows then x2 rows: 32768
#define NEG_BIG (-1e30f)

// ---------------------------------------------------------------------------
// Device-global scratch (no allocations allowed anywhere)
// ---------------------------------------------------------------------------
__device__ __nv_bfloat16 g_xh[(size_t)MROWS * HD];     // split(x1;x2) hi   48MB
__device__ __nv_bfloat16 g_xl[(size_t)MROWS * HD];     // split(x1;x2) lo   48MB
__device__ __nv_bfloat16 g_Wh[HD * HD];                // split(W) hi
__device__ __nv_bfloat16 g_Wl[HD * HD];                // split(W) lo
__device__ __nv_bfloat16 g_ph[(size_t)MROWS * HD];     // relu proj hi      48MB
__device__ __nv_bfloat16 g_pl[(size_t)MROWS * HD];     // relu proj lo      48MB
__device__ float         g_sc[(size_t)BSZ * L1D * L2D];        // scores     64MB
__device__ __nv_bfloat16 g_Ph[(size_t)BSZ * L1D * L2D];        // softmax hi 32MB
__device__ __nv_bfloat16 g_Pl[(size_t)BSZ * L1D * L2D];        // softmax lo 32MB
__device__ __nv_bfloat16 g_x2th[(size_t)BSZ * HD * L2D];       // x2^T hi    24MB
__device__ __nv_bfloat16 g_x2tl[(size_t)BSZ * HD * L2D];       // x2^T lo    24MB
__device__ float         g_maskbias[BSZ * L2D];
__device__ int           g_mask_is_i32;

// ---------------------------------------------------------------------------
// PTX helpers (sm_80-era: ldmatrix + mma.sync + cp.async — valid on compute_103)
// ---------------------------------------------------------------------------
__device__ __forceinline__ uint32_t smem_u32(const void* p) {
    uint32_t a;
    asm("{ .reg .u64 t; cvta.to.shared.u64 t, %1; cvt.u32.u64 %0, t; }"
        : "=r"(a) : "l"(p));
    return a;
}

#define CP_ASYNC16(saddr, gptr) \
    asm volatile("cp.async.cg.shared.global [%0], [%1], 16;" \
                 :: "r"(saddr), "l"(gptr) : "memory")
#define CP_COMMIT() asm volatile("cp.async.commit_group;" ::: "memory")
#define CP_WAIT0()  asm volatile("cp.async.wait_group 0;" ::: "memory")
#define CP_WAIT1()  asm volatile("cp.async.wait_group 1;" ::: "memory")

#define LDMATRIX_X4(f, addr) \
    asm volatile("ldmatrix.sync.aligned.m8n8.x4.shared.b16 {%0,%1,%2,%3}, [%4];" \
                 : "=r"((f)[0]), "=r"((f)[1]), "=r"((f)[2]), "=r"((f)[3]) \
                 : "r"(addr))

#define MMA_BF16(c, a, b0, b1) \
    asm volatile("mma.sync.aligned.m16n8k16.row.col.f32.bf16.bf16.f32 " \
                 "{%0,%1,%2,%3}, {%4,%5,%6,%7}, {%8,%9}, {%0,%1,%2,%3};" \
                 : "+f"((c)[0]), "+f"((c)[1]), "+f"((c)[2]), "+f"((c)[3]) \
                 : "r"((a)[0]), "r"((a)[1]), "r"((a)[2]), "r"((a)[3]), \
                   "r"(b0), "r"(b1))

// ---------------------------------------------------------------------------
// Small prep kernels
// ---------------------------------------------------------------------------
__global__ void detect_mask_kernel(const unsigned char* __restrict__ m) {
    __shared__ int bad;
    if (threadIdx.x == 0) bad = 0;
    __syncthreads();
    for (int i = threadIdx.x; i < BSZ * L2D; i += blockDim.x)
        if ((i & 3) && m[i]) bad = 1;
    __syncthreads();
    if (threadIdx.x == 0) g_mask_is_i32 = bad ? 0 : 1;
}

__global__ void maskbias_kernel(const void* __restrict__ m) {
    int i = blockIdx.x * blockDim.x + threadIdx.x;
    if (i >= BSZ * L2D) return;
    bool masked;
    if (g_mask_is_i32) masked = ((const int*)m)[i] != 0;
    else               masked = ((const unsigned char*)m)[i] != 0;
    g_maskbias[i] = masked ? NEG_BIG : 0.0f;
}

__device__ __forceinline__ void split1(float v, __nv_bfloat16& h, __nv_bfloat16& l) {
    h = __float2bfloat16(v);
    l = __float2bfloat16(v - __bfloat162float(h));
}

__global__ void split_kernel(const float* __restrict__ src,
                             __nv_bfloat16* __restrict__ hi,
                             __nv_bfloat16* __restrict__ lo, int n4) {
    int i = blockIdx.x * blockDim.x + threadIdx.x;
    if (i >= n4) return;
    float4 v = ((const float4*)src)[i];
    __nv_bfloat16 h[4], l[4];
    split1(v.x, h[0], l[0]); split1(v.y, h[1], l[1]);
    split1(v.z, h[2], l[2]); split1(v.w, h[3], l[3]);
    uint2 hp, lp;
    hp.x = (uint32_t)__bfloat16_as_ushort(h[1]) << 16 | __bfloat16_as_ushort(h[0]);
    hp.y = (uint32_t)__bfloat16_as_ushort(h[3]) << 16 | __bfloat16_as_ushort(h[2]);
    lp.x = (uint32_t)__bfloat16_as_ushort(l[1]) << 16 | __bfloat16_as_ushort(l[0]);
    lp.y = (uint32_t)__bfloat16_as_ushort(l[3]) << 16 | __bfloat16_as_ushort(l[2]);
    ((uint2*)hi)[i] = hp;
    ((uint2*)lo)[i] = lp;
}

// x2[b,j,h] -> x2t[b,h,j] split into hi/lo
__global__ void transpose_split_kernel(const float* __restrict__ x2) {
    __shared__ float t[32][33];
    int b = blockIdx.z;
    int j0 = blockIdx.x * 32, h0 = blockIdx.y * 32;
    int tx = threadIdx.x, ty = threadIdx.y;
    for (int r = ty; r < 32; r += 8)
        t[r][tx] = x2[((size_t)b * L2D + j0 + r) * HD + h0 + tx];
    __syncthreads();
    for (int r = ty; r < 32; r += 8) {
        float v = t[tx][r];
        __nv_bfloat16 h, l;
        split1(v, h, l);
        size_t o = ((size_t)b * HD + h0 + r) * L2D + j0 + tx;
        g_x2th[o] = h;
        g_x2tl[o] = l;
    }
}

// ---------------------------------------------------------------------------
// HMMA GEMM: C[128,128] = sum_K (Ah+Al)(Bh+Bl)^T, dropping Al*Bl.
// A, B bf16 K-major. K chunks of 64. cp.async double-buffered.
// Smem: 2 buffers x 4 tiles (AH, AL, BH, BL), each 128 rows x 128B, SW128 swizzle.
// 8 warps = 2 (m) x 4 (n); warp tile 64 x 32 (m16n8k16 frags: 4 x 4).
// ---------------------------------------------------------------------------
#define T_AH 0
#define T_AL 16384
#define T_BH 32768
#define T_BL 49152
#define BUFB 65536
#define SMEM_GEMM (2 * BUFB + 1024)

__device__ __forceinline__ uint32_t sw128(uint32_t bo) {
    return bo ^ ((bo >> 3) & 0x70);
}

__device__ __forceinline__ void cp_tile64(const __nv_bfloat16* __restrict__ g,
                                          int ld, uint32_t sdst, int tid) {
    #pragma unroll
    for (int v = tid; v < 1024; v += 256) {
        int r = v >> 3, c8 = (v & 7) * 8;
        uint32_t bo = (uint32_t)(r * 128 + c8 * 2);
        CP_ASYNC16(sdst + sw128(bo), g + (size_t)r * ld + c8);
    }
}

__device__ __forceinline__ void mma_gemm(
    const __nv_bfloat16* __restrict__ Ah, const __nv_bfloat16* __restrict__ Al, int ldA,
    const __nv_bfloat16* __restrict__ Bh, const __nv_bfloat16* __restrict__ Bl, int ldB,
    int nk, uint32_t sb, int tid, float acc[4][4][4])
{
    const int lane = tid & 31;
    const int wid = tid >> 5;
    const int wm = wid >> 2;        // 0..1
    const int wn = wid & 3;         // 0..3

    // prefetch chunk 0
    cp_tile64(Ah, ldA, sb + T_AH, tid);
    cp_tile64(Al, ldA, sb + T_AL, tid);
    cp_tile64(Bh, ldB, sb + T_BH, tid);
    cp_tile64(Bl, ldB, sb + T_BL, tid);
    CP_COMMIT();

    const int arow = wm * 64 + (lane & 15);
    const int brow = wn * 32 + (lane & 15);
    const int khalf = (lane >> 4) * 16;   // byte offset within k16 step

    for (int c = 0; c < nk; ++c) {
        if (c + 1 < nk) {
            uint32_t nb = sb + ((c + 1) & 1) * BUFB;
            cp_tile64(Ah + (c + 1) * 64, ldA, nb + T_AH, tid);
            cp_tile64(Al + (c + 1) * 64, ldA, nb + T_AL, tid);
            cp_tile64(Bh + (c + 1) * 64, ldB, nb + T_BH, tid);
            cp_tile64(Bl + (c + 1) * 64, ldB, nb + T_BL, tid);
            CP_COMMIT();
            CP_WAIT1();
        } else {
            CP_WAIT0();
        }
        __syncthreads();

        const uint32_t base = sb + (c & 1) * BUFB;
        #pragma unroll
        for (int ks = 0; ks < 4; ++ks) {
            const uint32_t kb = ks * 32 + khalf;
            uint32_t ah[4][4], al[4][4];
            #pragma unroll
            for (int mi = 0; mi < 4; ++mi) {
                uint32_t bo = sw128((uint32_t)((arow + mi * 16) * 128 + kb));
                LDMATRIX_X4(ah[mi], base + T_AH + bo);
                LDMATRIX_X4(al[mi], base + T_AL + bo);
            }
            uint32_t bh[2][4], bl[2][4];
            #pragma unroll
            for (int gN = 0; gN < 2; ++gN) {
                uint32_t bo = sw128((uint32_t)((brow + gN * 16) * 128 + kb));
                LDMATRIX_X4(bh[gN], base + T_BH + bo);
                LDMATRIX_X4(bl[gN], base + T_BL + bo);
            }
            #pragma unroll
            for (int mi = 0; mi < 4; ++mi) {
                #pragma unroll
                for (int gN = 0; gN < 2; ++gN) {
                    #pragma unroll
                    for (int s = 0; s < 2; ++s) {
                        int ni = gN * 2 + s;
                        // hi*hi + hi*lo + lo*hi
                        MMA_BF16(acc[mi][ni], ah[mi], bh[gN][s], bh[gN][s + 2]);
                        MMA_BF16(acc[mi][ni], ah[mi], bl[gN][s], bl[gN][s + 2]);
                        MMA_BF16(acc[mi][ni], al[mi], bh[gN][s], bh[gN][s + 2]);
                    }
                }
            }
        }
        __syncthreads();
    }
}

// Epilogue index helper: thread owns (r, cp), (r, cp+1), (r+8, cp), (r+8, cp+1)
// within each 16x8 frag; m_frag = wm*64 + mi*16 + r; n_frag = wn*32 + ni*8 + cp.
#define EPI_SETUP()                                                           \
    const int lane = tid & 31, wid = tid >> 5;                                \
    const int wm = wid >> 2, wn = wid & 3;                                    \
    const int er = lane >> 2, ec = (lane & 3) * 2;

// ---------------------------------------------------------------------------
// GEMM 1: proj. rows = (x1;x2), cols = HD. epilogue: +bias, relu, split.
// ---------------------------------------------------------------------------
__global__ __launch_bounds__(256, 1)
void mma_proj_kernel(const float* __restrict__ bias)
{
    extern __shared__ char smraw[];
    char* smp = (char*)(((uintptr_t)smraw + 1023) & ~(uintptr_t)1023);
    uint32_t sb = smem_u32(smp);
    const int tid = threadIdx.x;
    const int m0 = blockIdx.x * 128, n0 = blockIdx.y * 128;

    float acc[4][4][4] = {};
    mma_gemm(g_xh + (size_t)m0 * HD, g_xl + (size_t)m0 * HD, HD,
             g_Wh + (size_t)n0 * HD, g_Wl + (size_t)n0 * HD, HD,
             HD / 64, sb, tid, acc);

    EPI_SETUP();
    #pragma unroll
    for (int mi = 0; mi < 4; ++mi) {
        #pragma unroll
        for (int ni = 0; ni < 4; ++ni) {
            int n = n0 + wn * 32 + ni * 8 + ec;
            float b0 = bias[n], b1 = bias[n + 1];
            #pragma unroll
            for (int h = 0; h < 2; ++h) {
                int m = m0 + wm * 64 + mi * 16 + er + h * 8;
                float v0 = fmaxf(acc[mi][ni][2 * h]     + b0, 0.f);
                float v1 = fmaxf(acc[mi][ni][2 * h + 1] + b1, 0.f);
                __nv_bfloat16 h0, l0, h1, l1;
                split1(v0, h0, l0); split1(v1, h1, l1);
                size_t o = (size_t)m * HD + n;
                *(uint32_t*)(g_ph + o) =
                    (uint32_t)__bfloat16_as_ushort(h1) << 16 | __bfloat16_as_ushort(h0);
                *(uint32_t*)(g_pl + o) =
                    (uint32_t)__bfloat16_as_ushort(l1) << 16 | __bfloat16_as_ushort(l0);
            }
        }
    }
}

// ---------------------------------------------------------------------------
// GEMM 2: scores. per batch: xp[1024,HD] x yp[1024,HD]^T + maskbias -> g_sc
// ---------------------------------------------------------------------------
__global__ __launch_bounds__(256, 1)
void mma_scores_kernel()
{
    extern __shared__ char smraw[];
    char* smp = (char*)(((uintptr_t)smraw + 1023) & ~(uintptr_t)1023);
    uint32_t sb = smem_u32(smp);
    const int tid = threadIdx.x;
    const int b = blockIdx.z;
    const int m0 = blockIdx.x * 128, n0 = blockIdx.y * 128;
    const size_t arow = (size_t)(b * L1D + m0) * HD;
    const size_t brow = (size_t)(BSZ * L1D + b * L2D + n0) * HD;

    float acc[4][4][4] = {};
    mma_gemm(g_ph + arow, g_pl + arow, HD,
             g_ph + brow, g_pl + brow, HD,
             HD / 64, sb, tid, acc);

    EPI_SETUP();
    const float* mb = g_maskbias + b * L2D;
    #pragma unroll
    for (int mi = 0; mi < 4; ++mi) {
        #pragma unroll
        for (int ni = 0; ni < 4; ++ni) {
            int n = n0 + wn * 32 + ni * 8 + ec;
            float b0 = mb[n], b1 = mb[n + 1];
            #pragma unroll
            for (int h = 0; h < 2; ++h) {
                int m = m0 + wm * 64 + mi * 16 + er + h * 8;
                float2 v = make_float2(acc[mi][ni][2 * h] + b0,
                                       acc[mi][ni][2 * h + 1] + b1);
                *(float2*)(g_sc + ((size_t)b * L1D + m) * L2D + n) = v;
            }
        }
    }
}

// ---------------------------------------------------------------------------
// softmax over last dim; writes P split to bf16 hi/lo
// ---------------------------------------------------------------------------
__global__ __launch_bounds__(256) void softmax_split_kernel()
{
    const int row = blockIdx.x;
    const float* p = g_sc + (size_t)row * L2D;
    __nv_bfloat16* ph = g_Ph + (size_t)row * L2D;
    __nv_bfloat16* pl = g_Pl + (size_t)row * L2D;
    const int t = threadIdx.x;
    __shared__ float red[8];

    float v[4];
    float mx = NEG_BIG;
    #pragma unroll
    for (int u = 0; u < 4; u++) { v[u] = p[t + u * 256]; mx = fmaxf(mx, v[u]); }
    #pragma unroll
    for (int o = 16; o > 0; o >>= 1) mx = fmaxf(mx, __shfl_xor_sync(~0u, mx, o));
    if ((t & 31) == 0) red[t >> 5] = mx;
    __syncthreads();
    if (t == 0) {
        float m = red[0];
        #pragma unroll
        for (int i = 1; i < 8; i++) m = fmaxf(m, red[i]);
        red[0] = m;
    }
    __syncthreads();
    mx = red[0];
    __syncthreads();

    float s = 0.f;
    #pragma unroll
    for (int u = 0; u < 4; u++) { v[u] = __expf(v[u] - mx); s += v[u]; }
    #pragma unroll
    for (int o = 16; o > 0; o >>= 1) s += __shfl_xor_sync(~0u, s, o);
    if ((t & 31) == 0) red[t >> 5] = s;
    __syncthreads();
    if (t == 0) {
        float m = 0.f;
        #pragma unroll
        for (int i = 0; i < 8; i++) m += red[i];
        red[0] = m;
    }
    __syncthreads();
    float inv = 1.0f / red[0];
    #pragma unroll
    for (int u = 0; u < 4; u++) {
        float pv = v[u] * inv;
        __nv_bfloat16 h, l;
        split1(pv, h, l);
        ph[t + u * 256] = h;
        pl[t + u * 256] = l;
    }
}

// ---------------------------------------------------------------------------
// GEMM 3: attn + concat. per batch: P[1024,1024] x x2t[HD,1024]^T -> att
// out[b,i] = [x1 | att | x1*att | x1-att]
// ---------------------------------------------------------------------------
__global__ __launch_bounds__(256, 1)
void mma_attn_kernel(const float* __restrict__ X1, float* __restrict__ Out)
{
    extern __shared__ char smraw[];
    char* smp = (char*)(((uintptr_t)smraw + 1023) & ~(uintptr_t)1023);
    uint32_t sb = smem_u32(smp);
    const int tid = threadIdx.x;
    const int b = blockIdx.z;
    const int m0 = blockIdx.x * 128, n0 = blockIdx.y * 128;
    const size_t arow = ((size_t)b * L1D + m0) * L2D;
    const size_t brow = ((size_t)b * HD + n0) * L2D;

    float acc[4][4][4] = {};
    mma_gemm(g_Ph + arow, g_Pl + arow, L2D,
             g_x2th + brow, g_x2tl + brow, L2D,
             L2D / 64, sb, tid, acc);

    EPI_SETUP();
    #pragma unroll
    for (int mi = 0; mi < 4; ++mi) {
        #pragma unroll
        for (int ni = 0; ni < 4; ++ni) {
            int n = n0 + wn * 32 + ni * 8 + ec;
            #pragma unroll
            for (int h = 0; h < 2; ++h) {
                int m = m0 + wm * 64 + mi * 16 + er + h * 8;
                const float* x1row = X1 + ((size_t)b * L1D + m) * HD;
                float* orow = Out + ((size_t)b * L1D + m) * (size_t)(4 * HD);
                float2 a = make_float2(acc[mi][ni][2 * h], acc[mi][ni][2 * h + 1]);
                float2 xv = *(const float2*)(x1row + n);
                *(float2*)(orow + n)          = xv;
                *(float2*)(orow + HD + n)     = a;
                *(float2*)(orow + 2 * HD + n) = make_float2(xv.x * a.x, xv.y * a.y);
                *(float2*)(orow + 3 * HD + n) = make_float2(xv.x - a.x, xv.y - a.y);
            }
        }
    }
}

// ---------------------------------------------------------------------------
extern "C" void kernel_launch(void* const* d_in, const int* in_sizes, int n_in,
                              void* d_out, int out_size)
{
    const float* x1      = (const float*)d_in[0];
    const float* x2      = (const float*)d_in[1];
    const void*  x2_mask = d_in[3];
    const float* W       = (const float*)d_in[4];
    const float* bias    = (const float*)d_in[5];
    float* out = (float*)d_out;
    (void)in_sizes; (void)n_in; (void)out_size;

    cudaFuncSetAttribute(mma_proj_kernel,   cudaFuncAttributeMaxDynamicSharedMemorySize, SMEM_GEMM);
    cudaFuncSetAttribute(mma_scores_kernel, cudaFuncAttributeMaxDynamicSharedMemorySize, SMEM_GEMM);
    cudaFuncSetAttribute(mma_attn_kernel,   cudaFuncAttributeMaxDynamicSharedMemorySize, SMEM_GEMM);

    detect_mask_kernel<<<1, 256>>>((const unsigned char*)x2_mask);
    maskbias_kernel<<<(BSZ * L2D + 255) / 256, 256>>>(x2_mask);

    // bf16 hi/lo splits
    {
        __nv_bfloat16 *xh, *xl, *wh, *wl;
        cudaGetSymbolAddress((void**)&xh, g_xh);
        cudaGetSymbolAddress((void**)&xl, g_xl);
        cudaGetSymbolAddress((void**)&wh, g_Wh);
        cudaGetSymbolAddress((void**)&wl, g_Wl);
        int n1 = BSZ * L1D * HD / 4;
        split_kernel<<<(n1 + 255) / 256, 256>>>(x1, xh, xl, n1);
        split_kernel<<<(n1 + 255) / 256, 256>>>(
            x2, xh + (size_t)BSZ * L1D * HD, xl + (size_t)BSZ * L1D * HD, n1);
        int nw = HD * HD / 4;
        split_kernel<<<(nw + 255) / 256, 256>>>(W, wh, wl, nw);
    }

    transpose_split_kernel<<<dim3(L2D / 32, HD / 32, BSZ), dim3(32, 8)>>>(x2);

    mma_proj_kernel<<<dim3(MROWS / 128, HD / 128), 256, SMEM_GEMM>>>(bias);

    mma_scores_kernel<<<dim3(L1D / 128, L2D / 128, BSZ), 256, SMEM_GEMM>>>();

    softmax_split_kernel<<<BSZ * L1D, 256>>>();

    mma_attn_kernel<<<dim3(L1D / 128, HD / 128, BSZ), 256, SMEM_GEMM>>>(x1, out);
}

// round 8
// speedup vs baseline: 2.6725x; 1.4455x over previous
#include <cuda_runtime.h>
#include <cuda_bf16.h>
#include <cstdint>

// Problem constants (Unidir_atten: B=16, L1=L2=1024, H=768)
#define BSZ 16
#define L1D 1024
#define L2D 1024
#define HD  768
#define MROWS (2 * BSZ * L1D)          // x1 rows then x2 rows: 32768
#define NEG_BIG (-1e30f)

// ---------------------------------------------------------------------------
// Device-global scratch (no allocations allowed anywhere)
// ---------------------------------------------------------------------------
__device__ __nv_bfloat16 g_xh[(size_t)MROWS * HD];     // split(x1;x2) hi   48MB
__device__ __nv_bfloat16 g_xl[(size_t)MROWS * HD];     // split(x1;x2) lo   48MB
__device__ __nv_bfloat16 g_Wh[HD * HD];                // split(W) hi
__device__ __nv_bfloat16 g_Wl[HD * HD];                // split(W) lo
__device__ __nv_bfloat16 g_ph[(size_t)MROWS * HD];     // relu proj hi      48MB
__device__ __nv_bfloat16 g_pl[(size_t)MROWS * HD];     // relu proj lo      48MB
__device__ float         g_sc[(size_t)BSZ * L1D * L2D];        // scores     64MB
__device__ __nv_bfloat16 g_Ph[(size_t)BSZ * L1D * L2D];        // softmax hi 32MB
__device__ __nv_bfloat16 g_Pl[(size_t)BSZ * L1D * L2D];        // softmax lo 32MB
__device__ __nv_bfloat16 g_x2th[(size_t)BSZ * HD * L2D];       // x2^T hi    24MB
__device__ __nv_bfloat16 g_x2tl[(size_t)BSZ * HD * L2D];       // x2^T lo    24MB
__device__ float         g_maskbias[BSZ * L2D];
__device__ int           g_mask_is_i32;

// ---------------------------------------------------------------------------
// PTX helpers (sm_80-era: ldmatrix + mma.sync + cp.async — valid on compute_103)
// ---------------------------------------------------------------------------
__device__ __forceinline__ uint32_t smem_u32(const void* p) {
    uint32_t a;
    asm("{ .reg .u64 t; cvta.to.shared.u64 t, %1; cvt.u32.u64 %0, t; }"
        : "=r"(a) : "l"(p));
    return a;
}

#define CP_ASYNC16(saddr, gptr) \
    asm volatile("cp.async.cg.shared.global [%0], [%1], 16;" \
                 :: "r"(saddr), "l"(gptr) : "memory")
#define CP_COMMIT() asm volatile("cp.async.commit_group;" ::: "memory")
#define CP_WAIT0()  asm volatile("cp.async.wait_group 0;" ::: "memory")
#define CP_WAIT1()  asm volatile("cp.async.wait_group 1;" ::: "memory")

#define LDMATRIX_X4(f, addr) \
    asm volatile("ldmatrix.sync.aligned.m8n8.x4.shared.b16 {%0,%1,%2,%3}, [%4];" \
                 : "=r"((f)[0]), "=r"((f)[1]), "=r"((f)[2]), "=r"((f)[3]) \
                 : "r"(addr))

#define MMA_BF16(c, a, b0, b1) \
    asm volatile("mma.sync.aligned.m16n8k16.row.col.f32.bf16.bf16.f32 " \
                 "{%0,%1,%2,%3}, {%4,%5,%6,%7}, {%8,%9}, {%0,%1,%2,%3};" \
                 : "+f"((c)[0]), "+f"((c)[1]), "+f"((c)[2]), "+f"((c)[3]) \
                 : "r"((a)[0]), "r"((a)[1]), "r"((a)[2]), "r"((a)[3]), \
                   "r"(b0), "r"(b1))

// ---------------------------------------------------------------------------
// Small prep kernels
// ---------------------------------------------------------------------------
__global__ void detect_mask_kernel(const unsigned char* __restrict__ m) {
    __shared__ int bad;
    if (threadIdx.x == 0) bad = 0;
    __syncthreads();
    for (int i = threadIdx.x; i < BSZ * L2D; i += blockDim.x)
        if ((i & 3) && m[i]) bad = 1;
    __syncthreads();
    if (threadIdx.x == 0) g_mask_is_i32 = bad ? 0 : 1;
}

__global__ void maskbias_kernel(const void* __restrict__ m) {
    int i = blockIdx.x * blockDim.x + threadIdx.x;
    if (i >= BSZ * L2D) return;
    bool masked;
    if (g_mask_is_i32) masked = ((const int*)m)[i] != 0;
    else               masked = ((const unsigned char*)m)[i] != 0;
    g_maskbias[i] = masked ? NEG_BIG : 0.0f;
}

__device__ __forceinline__ void split1(float v, __nv_bfloat16& h, __nv_bfloat16& l) {
    h = __float2bfloat16(v);
    l = __float2bfloat16(v - __bfloat162float(h));
}

__global__ void split_kernel(const float* __restrict__ src,
                             __nv_bfloat16* __restrict__ hi,
                             __nv_bfloat16* __restrict__ lo, int n4) {
    int i = blockIdx.x * blockDim.x + threadIdx.x;
    if (i >= n4) return;
    float4 v = ((const float4*)src)[i];
    __nv_bfloat16 h[4], l[4];
    split1(v.x, h[0], l[0]); split1(v.y, h[1], l[1]);
    split1(v.z, h[2], l[2]); split1(v.w, h[3], l[3]);
    uint2 hp, lp;
    hp.x = (uint32_t)__bfloat16_as_ushort(h[1]) << 16 | __bfloat16_as_ushort(h[0]);
    hp.y = (uint32_t)__bfloat16_as_ushort(h[3]) << 16 | __bfloat16_as_ushort(h[2]);
    lp.x = (uint32_t)__bfloat16_as_ushort(l[1]) << 16 | __bfloat16_as_ushort(l[0]);
    lp.y = (uint32_t)__bfloat16_as_ushort(l[3]) << 16 | __bfloat16_as_ushort(l[2]);
    ((uint2*)hi)[i] = hp;
    ((uint2*)lo)[i] = lp;
}

// x2[b,j,h] -> x2t[b,h,j] split into hi/lo
__global__ void transpose_split_kernel(const float* __restrict__ x2) {
    __shared__ float t[32][33];
    int b = blockIdx.z;
    int j0 = blockIdx.x * 32, h0 = blockIdx.y * 32;
    int tx = threadIdx.x, ty = threadIdx.y;
    for (int r = ty; r < 32; r += 8)
        t[r][tx] = x2[((size_t)b * L2D + j0 + r) * HD + h0 + tx];
    __syncthreads();
    for (int r = ty; r < 32; r += 8) {
        float v = t[tx][r];
        __nv_bfloat16 h, l;
        split1(v, h, l);
        size_t o = ((size_t)b * HD + h0 + r) * L2D + j0 + tx;
        g_x2th[o] = h;
        g_x2tl[o] = l;
    }
}

// ---------------------------------------------------------------------------
// HMMA GEMM: C[256,128] = sum_K (Ah+Al)(Bh+Bl)^T, dropping Al*Bl.
// A, B bf16 K-major. K chunks of 64. cp.async double-buffered.
// Smem per buffer: AH/AL 256x128B (32KB each), BH/BL 128x128B (16KB each) = 96KB.
// 8 warps = 4 (m) x 2 (n); warp tile 64 x 64 (m16n8k16 frags: 4 x 8).
// Per k16 step: 16 LDSM.x4, 96 MMAs -> 6:1 MMA:LDSM ratio.
// ---------------------------------------------------------------------------
#define T_AH 0
#define T_AL 32768
#define T_BH 65536
#define T_BL 81920
#define BUFB 98304
#define SMEM_GEMM (2 * BUFB + 1024)

__device__ __forceinline__ uint32_t sw128(uint32_t bo) {
    return bo ^ ((bo >> 3) & 0x70);
}

// rows x 64 bf16 columns -> SW128-swizzled 128B rows. rows*8 vectors of 16B.
template <int ROWS>
__device__ __forceinline__ void cp_tile64(const __nv_bfloat16* __restrict__ g,
                                          int ld, uint32_t sdst, int tid) {
    #pragma unroll
    for (int v = tid; v < ROWS * 8; v += 256) {
        int r = v >> 3, c8 = (v & 7) * 8;
        uint32_t bo = (uint32_t)(r * 128 + c8 * 2);
        CP_ASYNC16(sdst + sw128(bo), g + (size_t)r * ld + c8);
    }
}

__device__ __forceinline__ void cp_chunk(
    const __nv_bfloat16* Ah, const __nv_bfloat16* Al, int ldA,
    const __nv_bfloat16* Bh, const __nv_bfloat16* Bl, int ldB,
    uint32_t buf, int tid)
{
    cp_tile64<256>(Ah, ldA, buf + T_AH, tid);
    cp_tile64<256>(Al, ldA, buf + T_AL, tid);
    cp_tile64<128>(Bh, ldB, buf + T_BH, tid);
    cp_tile64<128>(Bl, ldB, buf + T_BL, tid);
}

__device__ __forceinline__ void mma_gemm(
    const __nv_bfloat16* __restrict__ Ah, const __nv_bfloat16* __restrict__ Al, int ldA,
    const __nv_bfloat16* __restrict__ Bh, const __nv_bfloat16* __restrict__ Bl, int ldB,
    int nk, uint32_t sb, int tid, float acc[4][8][4])
{
    const int lane = tid & 31;
    const int wid = tid >> 5;
    const int wm = wid >> 1;        // 0..3  (64-row slice)
    const int wn = wid & 1;         // 0..1  (64-col slice)

    // prefetch chunk 0
    cp_chunk(Ah, Al, ldA, Bh, Bl, ldB, sb, tid);
    CP_COMMIT();

    const int arow = wm * 64 + (lane & 15);
    const int brow0 = wn * 64 + (lane & 15);
    const int khalf = (lane >> 4) * 16;   // byte offset within k16 step

    for (int c = 0; c < nk; ++c) {
        if (c + 1 < nk) {
            uint32_t nb = sb + ((c + 1) & 1) * BUFB;
            cp_chunk(Ah + (c + 1) * 64, Al + (c + 1) * 64, ldA,
                     Bh + (c + 1) * 64, Bl + (c + 1) * 64, ldB, nb, tid);
            CP_COMMIT();
            CP_WAIT1();
        } else {
            CP_WAIT0();
        }
        __syncthreads();

        const uint32_t base = sb + (c & 1) * BUFB;
        #pragma unroll
        for (int ks = 0; ks < 4; ++ks) {
            const uint32_t kb = ks * 32 + khalf;
            uint32_t ah[4][4], al[4][4];
            #pragma unroll
            for (int mi = 0; mi < 4; ++mi) {
                uint32_t bo = sw128((uint32_t)((arow + mi * 16) * 128 + kb));
                LDMATRIX_X4(ah[mi], base + T_AH + bo);
                LDMATRIX_X4(al[mi], base + T_AL + bo);
            }
            #pragma unroll
            for (int gN = 0; gN < 4; ++gN) {
                uint32_t bh[4], bl[4];
                uint32_t bo = sw128((uint32_t)((brow0 + gN * 16) * 128 + kb));
                LDMATRIX_X4(bh, base + T_BH + bo);
                LDMATRIX_X4(bl, base + T_BL + bo);
                #pragma unroll
                for (int mi = 0; mi < 4; ++mi) {
                    #pragma unroll
                    for (int s = 0; s < 2; ++s) {
                        int ni = gN * 2 + s;
                        // hi*hi + hi*lo + lo*hi
                        MMA_BF16(acc[mi][ni], ah[mi], bh[s], bh[s + 2]);
                        MMA_BF16(acc[mi][ni], ah[mi], bl[s], bl[s + 2]);
                        MMA_BF16(acc[mi][ni], al[mi], bh[s], bh[s + 2]);
                    }
                }
            }
        }
        __syncthreads();
    }
}

// Epilogue index helper: thread owns (r, ec), (r, ec+1), (r+8, ec), (r+8, ec+1)
// within each 16x8 frag; m = m0 + wm*64 + mi*16 + er (+8); n = n0 + wn*64 + ni*8 + ec.
#define EPI_SETUP()                                                           \
    const int lane = tid & 31, wid = tid >> 5;                                \
    const int wm = wid >> 1, wn = wid & 1;                                    \
    const int er = lane >> 2, ec = (lane & 3) * 2;

// ---------------------------------------------------------------------------
// GEMM 1: proj. rows = (x1;x2), cols = HD. epilogue: +bias, relu, split.
// ---------------------------------------------------------------------------
__global__ __launch_bounds__(256, 1)
void mma_proj_kernel(const float* __restrict__ bias)
{
    extern __shared__ char smraw[];
    char* smp = (char*)(((uintptr_t)smraw + 1023) & ~(uintptr_t)1023);
    uint32_t sb = smem_u32(smp);
    const int tid = threadIdx.x;
    const int m0 = blockIdx.x * 256, n0 = blockIdx.y * 128;

    float acc[4][8][4] = {};
    mma_gemm(g_xh + (size_t)m0 * HD, g_xl + (size_t)m0 * HD, HD,
             g_Wh + (size_t)n0 * HD, g_Wl + (size_t)n0 * HD, HD,
             HD / 64, sb, tid, acc);

    EPI_SETUP();
    #pragma unroll
    for (int mi = 0; mi < 4; ++mi) {
        #pragma unroll
        for (int ni = 0; ni < 8; ++ni) {
            int n = n0 + wn * 64 + ni * 8 + ec;
            float b0 = bias[n], b1 = bias[n + 1];
            #pragma unroll
            for (int h = 0; h < 2; ++h) {
                int m = m0 + wm * 64 + mi * 16 + er + h * 8;
                float v0 = fmaxf(acc[mi][ni][2 * h]     + b0, 0.f);
                float v1 = fmaxf(acc[mi][ni][2 * h + 1] + b1, 0.f);
                __nv_bfloat16 h0, l0, h1, l1;
                split1(v0, h0, l0); split1(v1, h1, l1);
                size_t o = (size_t)m * HD + n;
                *(uint32_t*)(g_ph + o) =
                    (uint32_t)__bfloat16_as_ushort(h1) << 16 | __bfloat16_as_ushort(h0);
                *(uint32_t*)(g_pl + o) =
                    (uint32_t)__bfloat16_as_ushort(l1) << 16 | __bfloat16_as_ushort(l0);
            }
        }
    }
}

// ---------------------------------------------------------------------------
// GEMM 2: scores. per batch: xp[1024,HD] x yp[1024,HD]^T + maskbias -> g_sc
// ---------------------------------------------------------------------------
__global__ __launch_bounds__(256, 1)
void mma_scores_kernel()
{
    extern __shared__ char smraw[];
    char* smp = (char*)(((uintptr_t)smraw + 1023) & ~(uintptr_t)1023);
    uint32_t sb = smem_u32(smp);
    const int tid = threadIdx.x;
    const int b = blockIdx.z;
    const int m0 = blockIdx.x * 256, n0 = blockIdx.y * 128;
    const size_t arow = (size_t)(b * L1D + m0) * HD;
    const size_t brow = (size_t)(BSZ * L1D + b * L2D + n0) * HD;

    float acc[4][8][4] = {};
    mma_gemm(g_ph + arow, g_pl + arow, HD,
             g_ph + brow, g_pl + brow, HD,
             HD / 64, sb, tid, acc);

    EPI_SETUP();
    const float* mb = g_maskbias + b * L2D;
    #pragma unroll
    for (int mi = 0; mi < 4; ++mi) {
        #pragma unroll
        for (int ni = 0; ni < 8; ++ni) {
            int n = n0 + wn * 64 + ni * 8 + ec;
            float b0 = mb[n], b1 = mb[n + 1];
            #pragma unroll
            for (int h = 0; h < 2; ++h) {
                int m = m0 + wm * 64 + mi * 16 + er + h * 8;
                float2 v = make_float2(acc[mi][ni][2 * h] + b0,
                                       acc[mi][ni][2 * h + 1] + b1);
                *(float2*)(g_sc + ((size_t)b * L1D + m) * L2D + n) = v;
            }
        }
    }
}

// ---------------------------------------------------------------------------
// softmax over last dim; writes P split to bf16 hi/lo
// ---------------------------------------------------------------------------
__global__ __launch_bounds__(256) void softmax_split_kernel()
{
    const int row = blockIdx.x;
    const float* p = g_sc + (size_t)row * L2D;
    __nv_bfloat16* ph = g_Ph + (size_t)row * L2D;
    __nv_bfloat16* pl = g_Pl + (size_t)row * L2D;
    const int t = threadIdx.x;
    __shared__ float red[8];

    float v[4];
    float mx = NEG_BIG;
    #pragma unroll
    for (int u = 0; u < 4; u++) { v[u] = p[t + u * 256]; mx = fmaxf(mx, v[u]); }
    #pragma unroll
    for (int o = 16; o > 0; o >>= 1) mx = fmaxf(mx, __shfl_xor_sync(~0u, mx, o));
    if ((t & 31) == 0) red[t >> 5] = mx;
    __syncthreads();
    if (t == 0) {
        float m = red[0];
        #pragma unroll
        for (int i = 1; i < 8; i++) m = fmaxf(m, red[i]);
        red[0] = m;
    }
    __syncthreads();
    mx = red[0];
    __syncthreads();

    float s = 0.f;
    #pragma unroll
    for (int u = 0; u < 4; u++) { v[u] = __expf(v[u] - mx); s += v[u]; }
    #pragma unroll
    for (int o = 16; o > 0; o >>= 1) s += __shfl_xor_sync(~0u, s, o);
    if ((t & 31) == 0) red[t >> 5] = s;
    __syncthreads();
    if (t == 0) {
        float m = 0.f;
        #pragma unroll
        for (int i = 0; i < 8; i++) m += red[i];
        red[0] = m;
    }
    __syncthreads();
    float inv = 1.0f / red[0];
    #pragma unroll
    for (int u = 0; u < 4; u++) {
        float pv = v[u] * inv;
        __nv_bfloat16 h, l;
        split1(pv, h, l);
        ph[t + u * 256] = h;
        pl[t + u * 256] = l;
    }
}

// ---------------------------------------------------------------------------
// GEMM 3: attn + concat. per batch: P[1024,1024] x x2t[HD,1024]^T -> att
// out[b,i] = [x1 | att | x1*att | x1-att]
// ---------------------------------------------------------------------------
__global__ __launch_bounds__(256, 1)
void mma_attn_kernel(const float* __restrict__ X1, float* __restrict__ Out)
{
    extern __shared__ char smraw[];
    char* smp = (char*)(((uintptr_t)smraw + 1023) & ~(uintptr_t)1023);
    uint32_t sb = smem_u32(smp);
    const int tid = threadIdx.x;
    const int b = blockIdx.z;
    const int m0 = blockIdx.x * 256, n0 = blockIdx.y * 128;
    const size_t arow = ((size_t)b * L1D + m0) * L2D;
    const size_t brow = ((size_t)b * HD + n0) * L2D;

    float acc[4][8][4] = {};
    mma_gemm(g_Ph + arow, g_Pl + arow, L2D,
             g_x2th + brow, g_x2tl + brow, L2D,
             L2D / 64, sb, tid, acc);

    EPI_SETUP();
    #pragma unroll
    for (int mi = 0; mi < 4; ++mi) {
        #pragma unroll
        for (int ni = 0; ni < 8; ++ni) {
            int n = n0 + wn * 64 + ni * 8 + ec;
            #pragma unroll
            for (int h = 0; h < 2; ++h) {
                int m = m0 + wm * 64 + mi * 16 + er + h * 8;
                const float* x1row = X1 + ((size_t)b * L1D + m) * HD;
                float* orow = Out + ((size_t)b * L1D + m) * (size_t)(4 * HD);
                float2 a = make_float2(acc[mi][ni][2 * h], acc[mi][ni][2 * h + 1]);
                float2 xv = *(const float2*)(x1row + n);
                *(float2*)(orow + n)          = xv;
                *(float2*)(orow + HD + n)     = a;
                *(float2*)(orow + 2 * HD + n) = make_float2(xv.x * a.x, xv.y * a.y);
                *(float2*)(orow + 3 * HD + n) = make_float2(xv.x - a.x, xv.y - a.y);
            }
        }
    }
}

// ---------------------------------------------------------------------------
extern "C" void kernel_launch(void* const* d_in, const int* in_sizes, int n_in,
                              void* d_out, int out_size)
{
    const float* x1      = (const float*)d_in[0];
    const float* x2      = (const float*)d_in[1];
    const void*  x2_mask = d_in[3];
    const float* W       = (const float*)d_in[4];
    const float* bias    = (const float*)d_in[5];
    float* out = (float*)d_out;
    (void)in_sizes; (void)n_in; (void)out_size;

    cudaFuncSetAttribute(mma_proj_kernel,   cudaFuncAttributeMaxDynamicSharedMemorySize, SMEM_GEMM);
    cudaFuncSetAttribute(mma_scores_kernel, cudaFuncAttributeMaxDynamicSharedMemorySize, SMEM_GEMM);
    cudaFuncSetAttribute(mma_attn_kernel,   cudaFuncAttributeMaxDynamicSharedMemorySize, SMEM_GEMM);

    detect_mask_kernel<<<1, 256>>>((const unsigned char*)x2_mask);
    maskbias_kernel<<<(BSZ * L2D + 255) / 256, 256>>>(x2_mask);

    // bf16 hi/lo splits
    {
        __nv_bfloat16 *xh, *xl, *wh, *wl;
        cudaGetSymbolAddress((void**)&xh, g_xh);
        cudaGetSymbolAddress((void**)&xl, g_xl);
        cudaGetSymbolAddress((void**)&wh, g_Wh);
        cudaGetSymbolAddress((void**)&wl, g_Wl);
        int n1 = BSZ * L1D * HD / 4;
        split_kernel<<<(n1 + 255) / 256, 256>>>(x1, xh, xl, n1);
        split_kernel<<<(n1 + 255) / 256, 256>>>(
            x2, xh + (size_t)BSZ * L1D * HD, xl + (size_t)BSZ * L1D * HD, n1);
        int nw = HD * HD / 4;
        split_kernel<<<(nw + 255) / 256, 256>>>(W, wh, wl, nw);
    }

    transpose_split_kernel<<<dim3(L2D / 32, HD / 32, BSZ), dim3(32, 8)>>>(x2);

    mma_proj_kernel<<<dim3(MROWS / 256, HD / 128), 256, SMEM_GEMM>>>(bias);

    mma_scores_kernel<<<dim3(L1D / 256, L2D / 128, BSZ), 256, SMEM_GEMM>>>();

    softmax_split_kernel<<<BSZ * L1D, 256>>>();

    mma_attn_kernel<<<dim3(L1D / 256, HD / 128, BSZ), 256, SMEM_GEMM>>>(x1, out);
}

// round 13
// speedup vs baseline: 2.7912x; 1.0444x over previous
#include <cuda_runtime.h>
#include <cuda_bf16.h>
#include <cstdint>

// Problem constants (Unidir_atten: B=16, L1=L2=1024, H=768)
#define BSZ 16
#define L1D 1024
#define L2D 1024
#define HD  768
#define MROWS (2 * BSZ * L1D)          // x1 rows then x2 rows: 32768
#define NEG_BIG (-1e30f)

// ---------------------------------------------------------------------------
// Device-global scratch (no allocations allowed anywhere)
// ---------------------------------------------------------------------------
__device__ __nv_bfloat16 g_xh[(size_t)MROWS * HD];     // split(x1;x2) hi   48MB
__device__ __nv_bfloat16 g_xl[(size_t)MROWS * HD];     // split(x1;x2) lo   48MB
__device__ __nv_bfloat16 g_Wh[HD * HD];                // split(W) hi
__device__ __nv_bfloat16 g_Wl[HD * HD];                // split(W) lo
__device__ __nv_bfloat16 g_ph[(size_t)MROWS * HD];     // relu proj hi      48MB
__device__ __nv_bfloat16 g_pl[(size_t)MROWS * HD];     // relu proj lo      48MB
__device__ float         g_sc[(size_t)BSZ * L1D * L2D];        // scores     64MB
__device__ __nv_bfloat16 g_Ph[(size_t)BSZ * L1D * L2D];        // softmax hi 32MB
__device__ __nv_bfloat16 g_Pl[(size_t)BSZ * L1D * L2D];        // softmax lo 32MB
__device__ __nv_bfloat16 g_x2th[(size_t)BSZ * HD * L2D];       // x2^T hi    24MB
__device__ __nv_bfloat16 g_x2tl[(size_t)BSZ * HD * L2D];       // x2^T lo    24MB
__device__ float         g_maskbias[BSZ * L2D];
__device__ int           g_mask_is_i32;

// ---------------------------------------------------------------------------
// PTX helpers (sm_80-era: ldmatrix + mma.sync + cp.async — valid on compute_103)
// ---------------------------------------------------------------------------
__device__ __forceinline__ uint32_t smem_u32(const void* p) {
    uint32_t a;
    asm("{ .reg .u64 t; cvta.to.shared.u64 t, %1; cvt.u32.u64 %0, t; }"
        : "=r"(a) : "l"(p));
    return a;
}

#define CP_ASYNC16(saddr, gptr) \
    asm volatile("cp.async.cg.shared.global [%0], [%1], 16;" \
                 :: "r"(saddr), "l"(gptr) : "memory")
#define CP_COMMIT() asm volatile("cp.async.commit_group;" ::: "memory")
#define CP_WAIT0()  asm volatile("cp.async.wait_group 0;" ::: "memory")
#define CP_WAIT1()  asm volatile("cp.async.wait_group 1;" ::: "memory")

#define LDMATRIX_X4(f, addr) \
    asm volatile("ldmatrix.sync.aligned.m8n8.x4.shared.b16 {%0,%1,%2,%3}, [%4];" \
                 : "=r"((f)[0]), "=r"((f)[1]), "=r"((f)[2]), "=r"((f)[3]) \
                 : "r"(addr))

#define MMA_BF16(c, a, b0, b1) \
    asm volatile("mma.sync.aligned.m16n8k16.row.col.f32.bf16.bf16.f32 " \
                 "{%0,%1,%2,%3}, {%4,%5,%6,%7}, {%8,%9}, {%0,%1,%2,%3};" \
                 : "+f"((c)[0]), "+f"((c)[1]), "+f"((c)[2]), "+f"((c)[3]) \
                 : "r"((a)[0]), "r"((a)[1]), "r"((a)[2]), "r"((a)[3]), \
                   "r"(b0), "r"(b1))

// ---------------------------------------------------------------------------
// Small prep kernels
// ---------------------------------------------------------------------------
__global__ void detect_mask_kernel(const unsigned char* __restrict__ m) {
    __shared__ int bad;
    if (threadIdx.x == 0) bad = 0;
    __syncthreads();
    for (int i = threadIdx.x; i < BSZ * L2D; i += blockDim.x)
        if ((i & 3) && m[i]) bad = 1;
    __syncthreads();
    if (threadIdx.x == 0) g_mask_is_i32 = bad ? 0 : 1;
}

__global__ void maskbias_kernel(const void* __restrict__ m) {
    int i = blockIdx.x * blockDim.x + threadIdx.x;
    if (i >= BSZ * L2D) return;
    bool masked;
    if (g_mask_is_i32) masked = ((const int*)m)[i] != 0;
    else               masked = ((const unsigned char*)m)[i] != 0;
    g_maskbias[i] = masked ? NEG_BIG : 0.0f;
}

__device__ __forceinline__ void split1(float v, __nv_bfloat16& h, __nv_bfloat16& l) {
    h = __float2bfloat16(v);
    l = __float2bfloat16(v - __bfloat162float(h));
}

// One launch splits x1, x2, W (concatenated logical index space, float4 units)
#define N4_X  (BSZ * L1D * HD / 4)
#define N4_W  (HD * HD / 4)
__global__ void split_all_kernel(const float* __restrict__ x1,
                                 const float* __restrict__ x2,
                                 const float* __restrict__ W) {
    int i = blockIdx.x * blockDim.x + threadIdx.x;
    const float* src;
    __nv_bfloat16 *hi, *lo;
    int idx;
    if (i < N4_X)               { src = x1; hi = g_xh; lo = g_xl; idx = i; }
    else if (i < 2 * N4_X)      { src = x2; hi = g_xh + (size_t)BSZ * L1D * HD;
                                  lo = g_xl + (size_t)BSZ * L1D * HD; idx = i - N4_X; }
    else if (i < 2 * N4_X + N4_W) { src = W; hi = g_Wh; lo = g_Wl; idx = i - 2 * N4_X; }
    else return;

    float4 v = ((const float4*)src)[idx];
    __nv_bfloat16 h[4], l[4];
    split1(v.x, h[0], l[0]); split1(v.y, h[1], l[1]);
    split1(v.z, h[2], l[2]); split1(v.w, h[3], l[3]);
    uint2 hp, lp;
    hp.x = (uint32_t)__bfloat16_as_ushort(h[1]) << 16 | __bfloat16_as_ushort(h[0]);
    hp.y = (uint32_t)__bfloat16_as_ushort(h[3]) << 16 | __bfloat16_as_ushort(h[2]);
    lp.x = (uint32_t)__bfloat16_as_ushort(l[1]) << 16 | __bfloat16_as_ushort(l[0]);
    lp.y = (uint32_t)__bfloat16_as_ushort(l[3]) << 16 | __bfloat16_as_ushort(l[2]);
    ((uint2*)hi)[idx] = hp;
    ((uint2*)lo)[idx] = lp;
}

// x2[b,j,h] -> x2t[b,h,j] split into hi/lo
__global__ void transpose_split_kernel(const float* __restrict__ x2) {
    __shared__ float t[32][33];
    int b = blockIdx.z;
    int j0 = blockIdx.x * 32, h0 = blockIdx.y * 32;
    int tx = threadIdx.x, ty = threadIdx.y;
    for (int r = ty; r < 32; r += 8)
        t[r][tx] = x2[((size_t)b * L2D + j0 + r) * HD + h0 + tx];
    __syncthreads();
    for (int r = ty; r < 32; r += 8) {
        float v = t[tx][r];
        __nv_bfloat16 h, l;
        split1(v, h, l);
        size_t o = ((size_t)b * HD + h0 + r) * L2D + j0 + tx;
        g_x2th[o] = h;
        g_x2tl[o] = l;
    }
}

// ---------------------------------------------------------------------------
// HMMA GEMM: C[256,128] = sum_K (Ah+Al)(Bh+Bl)^T, dropping Al*Bl.
// 8 warps = 4 (m) x 2 (n); warp tile 64 x 64. K chunks of 64, double-buffered.
// MMA issue order is PRODUCT-MAJOR: per gN, each of the 3 split products
// sweeps all 8 (mi,s) accumulators, so same-acc MMAs are 8 apart (ILP).
// ---------------------------------------------------------------------------
#define T_AH 0
#define T_AL 32768
#define T_BH 65536
#define T_BL 81920
#define BUFB 98304
#define SMEM_GEMM (2 * BUFB + 1024)

__device__ __forceinline__ uint32_t sw128(uint32_t bo) {
    return bo ^ ((bo >> 3) & 0x70);
}

template <int ROWS>
__device__ __forceinline__ void cp_tile64(const __nv_bfloat16* __restrict__ g,
                                          int ld, uint32_t sdst, int tid) {
    #pragma unroll
    for (int v = tid; v < ROWS * 8; v += 256) {
        int r = v >> 3, c8 = (v & 7) * 8;
        uint32_t bo = (uint32_t)(r * 128 + c8 * 2);
        CP_ASYNC16(sdst + sw128(bo), g + (size_t)r * ld + c8);
    }
}

__device__ __forceinline__ void cp_chunk(
    const __nv_bfloat16* Ah, const __nv_bfloat16* Al, int ldA,
    const __nv_bfloat16* Bh, const __nv_bfloat16* Bl, int ldB,
    uint32_t buf, int tid)
{
    cp_tile64<256>(Ah, ldA, buf + T_AH, tid);
    cp_tile64<256>(Al, ldA, buf + T_AL, tid);
    cp_tile64<128>(Bh, ldB, buf + T_BH, tid);
    cp_tile64<128>(Bl, ldB, buf + T_BL, tid);
}

__device__ __forceinline__ void mma_gemm(
    const __nv_bfloat16* __restrict__ Ah, const __nv_bfloat16* __restrict__ Al, int ldA,
    const __nv_bfloat16* __restrict__ Bh, const __nv_bfloat16* __restrict__ Bl, int ldB,
    int nk, uint32_t sb, int tid, float acc[4][8][4])
{
    const int lane = tid & 31;
    const int wid = tid >> 5;
    const int wm = wid >> 1;        // 0..3  (64-row slice)
    const int wn = wid & 1;         // 0..1  (64-col slice)

    // prefetch chunk 0
    cp_chunk(Ah, Al, ldA, Bh, Bl, ldB, sb, tid);
    CP_COMMIT();

    const int arow = wm * 64 + (lane & 15);
    const int brow0 = wn * 64 + (lane & 15);
    const int khalf = (lane >> 4) * 16;   // byte offset within k16 step

    for (int c = 0; c < nk; ++c) {
        if (c + 1 < nk) {
            uint32_t nb = sb + ((c + 1) & 1) * BUFB;
            cp_chunk(Ah + (c + 1) * 64, Al + (c + 1) * 64, ldA,
                     Bh + (c + 1) * 64, Bl + (c + 1) * 64, ldB, nb, tid);
            CP_COMMIT();
            CP_WAIT1();
        } else {
            CP_WAIT0();
        }
        __syncthreads();

        const uint32_t base = sb + (c & 1) * BUFB;
        #pragma unroll
        for (int ks = 0; ks < 4; ++ks) {
            const uint32_t kb = ks * 32 + khalf;
            uint32_t ah[4][4], al[4][4];
            #pragma unroll
            for (int mi = 0; mi < 4; ++mi) {
                uint32_t bo = sw128((uint32_t)((arow + mi * 16) * 128 + kb));
                LDMATRIX_X4(ah[mi], base + T_AH + bo);
                LDMATRIX_X4(al[mi], base + T_AL + bo);
            }
            #pragma unroll
            for (int gN = 0; gN < 4; ++gN) {
                uint32_t bh[4], bl[4];
                uint32_t bo = sw128((uint32_t)((brow0 + gN * 16) * 128 + kb));
                LDMATRIX_X4(bh, base + T_BH + bo);
                LDMATRIX_X4(bl, base + T_BL + bo);
                // product-major: 8 independent accs between same-acc reuses
                #pragma unroll
                for (int mi = 0; mi < 4; ++mi)
                    #pragma unroll
                    for (int s = 0; s < 2; ++s)
                        MMA_BF16(acc[mi][gN * 2 + s], ah[mi], bh[s], bh[s + 2]);
                #pragma unroll
                for (int mi = 0; mi < 4; ++mi)
                    #pragma unroll
                    for (int s = 0; s < 2; ++s)
                        MMA_BF16(acc[mi][gN * 2 + s], ah[mi], bl[s], bl[s + 2]);
                #pragma unroll
                for (int mi = 0; mi < 4; ++mi)
                    #pragma unroll
                    for (int s = 0; s < 2; ++s)
                        MMA_BF16(acc[mi][gN * 2 + s], al[mi], bh[s], bh[s + 2]);
            }
        }
        __syncthreads();
    }
}

#define EPI_SETUP()                                                           \
    const int lane = tid & 31, wid = tid >> 5;                                \
    const int wm = wid >> 1, wn = wid & 1;                                    \
    const int er = lane >> 2, ec = (lane & 3) * 2;

// ---------------------------------------------------------------------------
// GEMM 1: proj. rows = (x1;x2), cols = HD. epilogue: +bias, relu, split.
// ---------------------------------------------------------------------------
__global__ __launch_bounds__(256, 1)
void mma_proj_kernel(const float* __restrict__ bias)
{
    extern __shared__ char smraw[];
    char* smp = (char*)(((uintptr_t)smraw + 1023) & ~(uintptr_t)1023);
    uint32_t sb = smem_u32(smp);
    const int tid = threadIdx.x;
    const int m0 = blockIdx.x * 256, n0 = blockIdx.y * 128;

    float acc[4][8][4] = {};
    mma_gemm(g_xh + (size_t)m0 * HD, g_xl + (size_t)m0 * HD, HD,
             g_Wh + (size_t)n0 * HD, g_Wl + (size_t)n0 * HD, HD,
             HD / 64, sb, tid, acc);

    EPI_SETUP();
    #pragma unroll
    for (int mi = 0; mi < 4; ++mi) {
        #pragma unroll
        for (int ni = 0; ni < 8; ++ni) {
            int n = n0 + wn * 64 + ni * 8 + ec;
            float b0 = bias[n], b1 = bias[n + 1];
            #pragma unroll
            for (int h = 0; h < 2; ++h) {
                int m = m0 + wm * 64 + mi * 16 + er + h * 8;
                float v0 = fmaxf(acc[mi][ni][2 * h]     + b0, 0.f);
                float v1 = fmaxf(acc[mi][ni][2 * h + 1] + b1, 0.f);
                __nv_bfloat16 h0, l0, h1, l1;
                split1(v0, h0, l0); split1(v1, h1, l1);
                size_t o = (size_t)m * HD + n;
                *(uint32_t*)(g_ph + o) =
                    (uint32_t)__bfloat16_as_ushort(h1) << 16 | __bfloat16_as_ushort(h0);
                *(uint32_t*)(g_pl + o) =
                    (uint32_t)__bfloat16_as_ushort(l1) << 16 | __bfloat16_as_ushort(l0);
            }
        }
    }
}

// ---------------------------------------------------------------------------
// GEMM 2: scores. per batch: xp[1024,HD] x yp[1024,HD]^T + maskbias -> g_sc
// ---------------------------------------------------------------------------
__global__ __launch_bounds__(256, 1)
void mma_scores_kernel()
{
    extern __shared__ char smraw[];
    char* smp = (char*)(((uintptr_t)smraw + 1023) & ~(uintptr_t)1023);
    uint32_t sb = smem_u32(smp);
    const int tid = threadIdx.x;
    const int b = blockIdx.z;
    const int m0 = blockIdx.x * 256, n0 = blockIdx.y * 128;
    const size_t arow = (size_t)(b * L1D + m0) * HD;
    const size_t brow = (size_t)(BSZ * L1D + b * L2D + n0) * HD;

    float acc[4][8][4] = {};
    mma_gemm(g_ph + arow, g_pl + arow, HD,
             g_ph + brow, g_pl + brow, HD,
             HD / 64, sb, tid, acc);

    EPI_SETUP();
    const float* mb = g_maskbias + b * L2D;
    #pragma unroll
    for (int mi = 0; mi < 4; ++mi) {
        #pragma unroll
        for (int ni = 0; ni < 8; ++ni) {
            int n = n0 + wn * 64 + ni * 8 + ec;
            float b0 = mb[n], b1 = mb[n + 1];
            #pragma unroll
            for (int h = 0; h < 2; ++h) {
                int m = m0 + wm * 64 + mi * 16 + er + h * 8;
                float2 v = make_float2(acc[mi][ni][2 * h] + b0,
                                       acc[mi][ni][2 * h + 1] + b1);
                *(float2*)(g_sc + ((size_t)b * L1D + m) * L2D + n) = v;
            }
        }
    }
}

// ---------------------------------------------------------------------------
// softmax over last dim; writes P split to bf16 hi/lo
// ---------------------------------------------------------------------------
__global__ __launch_bounds__(256) void softmax_split_kernel()
{
    const int row = blockIdx.x;
    const float* p = g_sc + (size_t)row * L2D;
    __nv_bfloat16* ph = g_Ph + (size_t)row * L2D;
    __nv_bfloat16* pl = g_Pl + (size_t)row * L2D;
    const int t = threadIdx.x;
    __shared__ float red[8];

    float v[4];
    float mx = NEG_BIG;
    #pragma unroll
    for (int u = 0; u < 4; u++) { v[u] = p[t + u * 256]; mx = fmaxf(mx, v[u]); }
    #pragma unroll
    for (int o = 16; o > 0; o >>= 1) mx = fmaxf(mx, __shfl_xor_sync(~0u, mx, o));
    if ((t & 31) == 0) red[t >> 5] = mx;
    __syncthreads();
    if (t == 0) {
        float m = red[0];
        #pragma unroll
        for (int i = 1; i < 8; i++) m = fmaxf(m, red[i]);
        red[0] = m;
    }
    __syncthreads();
    mx = red[0];
    __syncthreads();

    float s = 0.f;
    #pragma unroll
    for (int u = 0; u < 4; u++) { v[u] = __expf(v[u] - mx); s += v[u]; }
    #pragma unroll
    for (int o = 16; o > 0; o >>= 1) s += __shfl_xor_sync(~0u, s, o);
    if ((t & 31) == 0) red[t >> 5] = s;
    __syncthreads();
    if (t == 0) {
        float m = 0.f;
        #pragma unroll
        for (int i = 0; i < 8; i++) m += red[i];
        red[0] = m;
    }
    __syncthreads();
    float inv = 1.0f / red[0];
    #pragma unroll
    for (int u = 0; u < 4; u++) {
        float pv = v[u] * inv;
        __nv_bfloat16 h, l;
        split1(pv, h, l);
        ph[t + u * 256] = h;
        pl[t + u * 256] = l;
    }
}

// ---------------------------------------------------------------------------
// GEMM 3: attn + concat. per batch: P[1024,1024] x x2t[HD,1024]^T -> att
// out[b,i] = [x1 | att | x1*att | x1-att]
// ---------------------------------------------------------------------------
__global__ __launch_bounds__(256, 1)
void mma_attn_kernel(const float* __restrict__ X1, float* __restrict__ Out)
{
    extern __shared__ char smraw[];
    char* smp = (char*)(((uintptr_t)smraw + 1023) & ~(uintptr_t)1023);
    uint32_t sb = smem_u32(smp);
    const int tid = threadIdx.x;
    const int b = blockIdx.z;
    const int m0 = blockIdx.x * 256, n0 = blockIdx.y * 128;
    const size_t arow = ((size_t)b * L1D + m0) * L2D;
    const size_t brow = ((size_t)b * HD + n0) * L2D;

    float acc[4][8][4] = {};
    mma_gemm(g_Ph + arow, g_Pl + arow, L2D,
             g_x2th + brow, g_x2tl + brow, L2D,
             L2D / 64, sb, tid, acc);

    EPI_SETUP();
    #pragma unroll
    for (int mi = 0; mi < 4; ++mi) {
        #pragma unroll
        for (int ni = 0; ni < 8; ++ni) {
            int n = n0 + wn * 64 + ni * 8 + ec;
            #pragma unroll
            for (int h = 0; h < 2; ++h) {
                int m = m0 + wm * 64 + mi * 16 + er + h * 8;
                const float* x1row = X1 + ((size_t)b * L1D + m) * HD;
                float* orow = Out + ((size_t)b * L1D + m) * (size_t)(4 * HD);
                float2 a = make_float2(acc[mi][ni][2 * h], acc[mi][ni][2 * h + 1]);
                float2 xv = *(const float2*)(x1row + n);
                *(float2*)(orow + n)          = xv;
                *(float2*)(orow + HD + n)     = a;
                *(float2*)(orow + 2 * HD + n) = make_float2(xv.x * a.x, xv.y * a.y);
                *(float2*)(orow + 3 * HD + n) = make_float2(xv.x - a.x, xv.y - a.y);
            }
        }
    }
}

// ---------------------------------------------------------------------------
extern "C" void kernel_launch(void* const* d_in, const int* in_sizes, int n_in,
                              void* d_out, int out_size)
{
    const float* x1      = (const float*)d_in[0];
    const float* x2      = (const float*)d_in[1];
    const void*  x2_mask = d_in[3];
    const float* W       = (const float*)d_in[4];
    const float* bias    = (const float*)d_in[5];
    float* out = (float*)d_out;
    (void)in_sizes; (void)n_in; (void)out_size;

    cudaFuncSetAttribute(mma_proj_kernel,   cudaFuncAttributeMaxDynamicSharedMemorySize, SMEM_GEMM);
    cudaFuncSetAttribute(mma_scores_kernel, cudaFuncAttributeMaxDynamicSharedMemorySize, SMEM_GEMM);
    cudaFuncSetAttribute(mma_attn_kernel,   cudaFuncAttributeMaxDynamicSharedMemorySize, SMEM_GEMM);

    // Launch order fixed so ncu (-s 5 -c 1) captures mma_scores_kernel:
    // 0 detect, 1 maskbias, 2 split_all, 3 transpose, 4 proj, 5 scores, ...
    detect_mask_kernel<<<1, 256>>>((const unsigned char*)x2_mask);
    maskbias_kernel<<<(BSZ * L2D + 255) / 256, 256>>>(x2_mask);

    int ntot4 = 2 * N4_X + N4_W;
    split_all_kernel<<<(ntot4 + 255) / 256, 256>>>(x1, x2, W);

    transpose_split_kernel<<<dim3(L2D / 32, HD / 32, BSZ), dim3(32, 8)>>>(x2);

    mma_proj_kernel<<<dim3(MROWS / 256, HD / 128), 256, SMEM_GEMM>>>(bias);

    mma_scores_kernel<<<dim3(L1D / 256, L2D / 128, BSZ), 256, SMEM_GEMM>>>();

    softmax_split_kernel<<<BSZ * L1D, 256>>>();

    mma_attn_kernel<<<dim3(L1D / 256, HD / 128, BSZ), 256, SMEM_GEMM>>>(x1, out);
}

// round 15
// speedup vs baseline: 2.8661x; 1.0269x over previous
#include <cuda_runtime.h>
#include <cuda_bf16.h>
#include <cstdint>

// Problem constants (Unidir_atten: B=16, L1=L2=1024, H=768)
#define BSZ 16
#define L1D 1024
#define L2D 1024
#define HD  768
#define MROWS (2 * BSZ * L1D)          // x1 rows then x2 rows: 32768
#define NEG_BIG (-1e30f)

// ---------------------------------------------------------------------------
// Device-global scratch (no allocations allowed anywhere)
// ---------------------------------------------------------------------------
__device__ __nv_bfloat16 g_xh[(size_t)MROWS * HD];     // split(x1;x2) hi   48MB
__device__ __nv_bfloat16 g_xl[(size_t)MROWS * HD];     // split(x1;x2) lo   48MB
__device__ __nv_bfloat16 g_Wh[HD * HD];                // split(W) hi
__device__ __nv_bfloat16 g_Wl[HD * HD];                // split(W) lo
__device__ __nv_bfloat16 g_ph[(size_t)MROWS * HD];     // relu proj hi      48MB
__device__ __nv_bfloat16 g_pl[(size_t)MROWS * HD];     // relu proj lo      48MB
__device__ float         g_sc[(size_t)BSZ * L1D * L2D];        // scores     64MB
__device__ __nv_bfloat16 g_Ph[(size_t)BSZ * L1D * L2D];        // softmax hi 32MB
__device__ __nv_bfloat16 g_Pl[(size_t)BSZ * L1D * L2D];        // softmax lo 32MB
__device__ __nv_bfloat16 g_x2th[(size_t)BSZ * HD * L2D];       // x2^T hi    24MB
__device__ __nv_bfloat16 g_x2tl[(size_t)BSZ * HD * L2D];       // x2^T lo    24MB
__device__ float         g_maskbias[BSZ * L2D];

// ---------------------------------------------------------------------------
// PTX helpers (sm_80-era: ldmatrix + mma.sync + cp.async — valid on compute_103)
// ---------------------------------------------------------------------------
__device__ __forceinline__ uint32_t smem_u32(const void* p) {
    uint32_t a;
    asm("{ .reg .u64 t; cvta.to.shared.u64 t, %1; cvt.u32.u64 %0, t; }"
        : "=r"(a) : "l"(p));
    return a;
}

#define CP_ASYNC16(saddr, gptr) \
    asm volatile("cp.async.cg.shared.global [%0], [%1], 16;" \
                 :: "r"(saddr), "l"(gptr) : "memory")
#define CP_COMMIT() asm volatile("cp.async.commit_group;" ::: "memory")
#define CP_WAIT0()  asm volatile("cp.async.wait_group 0;" ::: "memory")
#define CP_WAIT1()  asm volatile("cp.async.wait_group 1;" ::: "memory")

#define LDMATRIX_X4(f, addr) \
    asm volatile("ldmatrix.sync.aligned.m8n8.x4.shared.b16 {%0,%1,%2,%3}, [%4];" \
                 : "=r"((f)[0]), "=r"((f)[1]), "=r"((f)[2]), "=r"((f)[3]) \
                 : "r"(addr))

#define MMA_BF16(c, a, b0, b1) \
    asm volatile("mma.sync.aligned.m16n8k16.row.col.f32.bf16.bf16.f32 " \
                 "{%0,%1,%2,%3}, {%4,%5,%6,%7}, {%8,%9}, {%0,%1,%2,%3};" \
                 : "+f"((c)[0]), "+f"((c)[1]), "+f"((c)[2]), "+f"((c)[3]) \
                 : "r"((a)[0]), "r"((a)[1]), "r"((a)[2]), "r"((a)[3]), \
                   "r"(b0), "r"(b1))

// ---------------------------------------------------------------------------
// Combined mask kernel: one block, detect i8-vs-i32, then write bias.
// ---------------------------------------------------------------------------
__global__ __launch_bounds__(1024) void mask_kernel(const void* __restrict__ mp) {
    __shared__ int is_i32;
    const unsigned char* m = (const unsigned char*)mp;
    if (threadIdx.x == 0) is_i32 = 1;
    __syncthreads();
    for (int i = threadIdx.x; i < BSZ * L2D; i += 1024)
        if ((i & 3) && m[i]) is_i32 = 0;
    __syncthreads();
    bool i32 = (is_i32 != 0);
    for (int i = threadIdx.x; i < BSZ * L2D; i += 1024) {
        bool masked = i32 ? (((const int*)mp)[i] != 0) : (m[i] != 0);
        g_maskbias[i] = masked ? NEG_BIG : 0.0f;
    }
}

__device__ __forceinline__ void split1(float v, __nv_bfloat16& h, __nv_bfloat16& l) {
    h = __float2bfloat16(v);
    l = __float2bfloat16(v - __bfloat162float(h));
}

// One launch splits x1, x2, W (concatenated logical index space, float4 units)
#define N4_X  (BSZ * L1D * HD / 4)
#define N4_W  (HD * HD / 4)
__global__ void split_all_kernel(const float* __restrict__ x1,
                                 const float* __restrict__ x2,
                                 const float* __restrict__ W) {
    int i = blockIdx.x * blockDim.x + threadIdx.x;
    const float* src;
    __nv_bfloat16 *hi, *lo;
    int idx;
    if (i < N4_X)               { src = x1; hi = g_xh; lo = g_xl; idx = i; }
    else if (i < 2 * N4_X)      { src = x2; hi = g_xh + (size_t)BSZ * L1D * HD;
                                  lo = g_xl + (size_t)BSZ * L1D * HD; idx = i - N4_X; }
    else if (i < 2 * N4_X + N4_W) { src = W; hi = g_Wh; lo = g_Wl; idx = i - 2 * N4_X; }
    else return;

    float4 v = ((const float4*)src)[idx];
    __nv_bfloat16 h[4], l[4];
    split1(v.x, h[0], l[0]); split1(v.y, h[1], l[1]);
    split1(v.z, h[2], l[2]); split1(v.w, h[3], l[3]);
    uint2 hp, lp;
    hp.x = (uint32_t)__bfloat16_as_ushort(h[1]) << 16 | __bfloat16_as_ushort(h[0]);
    hp.y = (uint32_t)__bfloat16_as_ushort(h[3]) << 16 | __bfloat16_as_ushort(h[2]);
    lp.x = (uint32_t)__bfloat16_as_ushort(l[1]) << 16 | __bfloat16_as_ushort(l[0]);
    lp.y = (uint32_t)__bfloat16_as_ushort(l[3]) << 16 | __bfloat16_as_ushort(l[2]);
    ((uint2*)hi)[idx] = hp;
    ((uint2*)lo)[idx] = lp;
}

// x2[b,j,h] -> x2t[b,h,j] split into hi/lo
__global__ void transpose_split_kernel(const float* __restrict__ x2) {
    __shared__ float t[32][33];
    int b = blockIdx.z;
    int j0 = blockIdx.x * 32, h0 = blockIdx.y * 32;
    int tx = threadIdx.x, ty = threadIdx.y;
    for (int r = ty; r < 32; r += 8)
        t[r][tx] = x2[((size_t)b * L2D + j0 + r) * HD + h0 + tx];
    __syncthreads();
    for (int r = ty; r < 32; r += 8) {
        float v = t[tx][r];
        __nv_bfloat16 h, l;
        split1(v, h, l);
        size_t o = ((size_t)b * HD + h0 + r) * L2D + j0 + tx;
        g_x2th[o] = h;
        g_x2tl[o] = l;
    }
}

// ---------------------------------------------------------------------------
// HMMA GEMM: C[256,128] = sum_K (Ah+Al)(Bh+Bl)^T, dropping Al*Bl.
// 8 warps = 4 (m) x 2 (n); warp tile 64 x 64. K chunks of 64, double-buffered.
// ---------------------------------------------------------------------------
#define T_AH 0
#define T_AL 32768
#define T_BH 65536
#define T_BL 81920
#define BUFB 98304
#define SMEM_GEMM (2 * BUFB + 1024)

__device__ __forceinline__ uint32_t sw128(uint32_t bo) {
    return bo ^ ((bo >> 3) & 0x70);
}

template <int ROWS>
__device__ __forceinline__ void cp_tile64(const __nv_bfloat16* __restrict__ g,
                                          int ld, uint32_t sdst, int tid) {
    #pragma unroll
    for (int v = tid; v < ROWS * 8; v += 256) {
        int r = v >> 3, c8 = (v & 7) * 8;
        uint32_t bo = (uint32_t)(r * 128 + c8 * 2);
        CP_ASYNC16(sdst + sw128(bo), g + (size_t)r * ld + c8);
    }
}

__device__ __forceinline__ void cp_chunk(
    const __nv_bfloat16* Ah, const __nv_bfloat16* Al, int ldA,
    const __nv_bfloat16* Bh, const __nv_bfloat16* Bl, int ldB,
    uint32_t buf, int tid)
{
    cp_tile64<256>(Ah, ldA, buf + T_AH, tid);
    cp_tile64<256>(Al, ldA, buf + T_AL, tid);
    cp_tile64<128>(Bh, ldB, buf + T_BH, tid);
    cp_tile64<128>(Bl, ldB, buf + T_BL, tid);
}

__device__ __forceinline__ void mma_gemm(
    const __nv_bfloat16* __restrict__ Ah, const __nv_bfloat16* __restrict__ Al, int ldA,
    const __nv_bfloat16* __restrict__ Bh, const __nv_bfloat16* __restrict__ Bl, int ldB,
    int nk, uint32_t sb, int tid, float acc[4][8][4])
{
    const int lane = tid & 31;
    const int wid = tid >> 5;
    const int wm = wid >> 1;        // 0..3  (64-row slice)
    const int wn = wid & 1;         // 0..1  (64-col slice)

    cp_chunk(Ah, Al, ldA, Bh, Bl, ldB, sb, tid);
    CP_COMMIT();

    const int arow = wm * 64 + (lane & 15);
    const int brow0 = wn * 64 + (lane & 15);
    const int khalf = (lane >> 4) * 16;

    for (int c = 0; c < nk; ++c) {
        if (c + 1 < nk) {
            uint32_t nb = sb + ((c + 1) & 1) * BUFB;
            cp_chunk(Ah + (c + 1) * 64, Al + (c + 1) * 64, ldA,
                     Bh + (c + 1) * 64, Bl + (c + 1) * 64, ldB, nb, tid);
            CP_COMMIT();
            CP_WAIT1();
        } else {
            CP_WAIT0();
        }
        __syncthreads();

        const uint32_t base = sb + (c & 1) * BUFB;
        #pragma unroll
        for (int ks = 0; ks < 4; ++ks) {
            const uint32_t kb = ks * 32 + khalf;
            uint32_t ah[4][4], al[4][4];
            #pragma unroll
            for (int mi = 0; mi < 4; ++mi) {
                uint32_t bo = sw128((uint32_t)((arow + mi * 16) * 128 + kb));
                LDMATRIX_X4(ah[mi], base + T_AH + bo);
                LDMATRIX_X4(al[mi], base + T_AL + bo);
            }
            #pragma unroll
            for (int gN = 0; gN < 4; ++gN) {
                uint32_t bh[4], bl[4];
                uint32_t bo = sw128((uint32_t)((brow0 + gN * 16) * 128 + kb));
                LDMATRIX_X4(bh, base + T_BH + bo);
                LDMATRIX_X4(bl, base + T_BL + bo);
                // product-major: 8 independent accs between same-acc reuses
                #pragma unroll
                for (int mi = 0; mi < 4; ++mi)
                    #pragma unroll
                    for (int s = 0; s < 2; ++s)
                        MMA_BF16(acc[mi][gN * 2 + s], ah[mi], bh[s], bh[s + 2]);
                #pragma unroll
                for (int mi = 0; mi < 4; ++mi)
                    #pragma unroll
                    for (int s = 0; s < 2; ++s)
                        MMA_BF16(acc[mi][gN * 2 + s], ah[mi], bl[s], bl[s + 2]);
                #pragma unroll
                for (int mi = 0; mi < 4; ++mi)
                    #pragma unroll
                    for (int s = 0; s < 2; ++s)
                        MMA_BF16(acc[mi][gN * 2 + s], al[mi], bh[s], bh[s + 2]);
            }
        }
        __syncthreads();
    }
}

#define EPI_SETUP()                                                           \
    const int lane = tid & 31, wid = tid >> 5;                                \
    const int wm = wid >> 1, wn = wid & 1;                                    \
    const int er = lane >> 2, ec = (lane & 3) * 2;

// ---------------------------------------------------------------------------
// GEMM 1: proj. rows = (x1;x2), cols = HD. epilogue: +bias, relu, split.
// Grid: x = N blocks (6, FASTEST) -> concurrent CTAs share A tiles in L2.
// ---------------------------------------------------------------------------
__global__ __launch_bounds__(256, 1)
void mma_proj_kernel(const float* __restrict__ bias)
{
    extern __shared__ char smraw[];
    char* smp = (char*)(((uintptr_t)smraw + 1023) & ~(uintptr_t)1023);
    uint32_t sb = smem_u32(smp);
    const int tid = threadIdx.x;
    const int m0 = blockIdx.y * 256, n0 = blockIdx.x * 128;   // N fastest

    float acc[4][8][4] = {};
    mma_gemm(g_xh + (size_t)m0 * HD, g_xl + (size_t)m0 * HD, HD,
             g_Wh + (size_t)n0 * HD, g_Wl + (size_t)n0 * HD, HD,
             HD / 64, sb, tid, acc);

    EPI_SETUP();
    #pragma unroll
    for (int mi = 0; mi < 4; ++mi) {
        #pragma unroll
        for (int ni = 0; ni < 8; ++ni) {
            int n = n0 + wn * 64 + ni * 8 + ec;
            float b0 = bias[n], b1 = bias[n + 1];
            #pragma unroll
            for (int h = 0; h < 2; ++h) {
                int m = m0 + wm * 64 + mi * 16 + er + h * 8;
                float v0 = fmaxf(acc[mi][ni][2 * h]     + b0, 0.f);
                float v1 = fmaxf(acc[mi][ni][2 * h + 1] + b1, 0.f);
                __nv_bfloat16 h0, l0, h1, l1;
                split1(v0, h0, l0); split1(v1, h1, l1);
                size_t o = (size_t)m * HD + n;
                *(uint32_t*)(g_ph + o) =
                    (uint32_t)__bfloat16_as_ushort(h1) << 16 | __bfloat16_as_ushort(h0);
                *(uint32_t*)(g_pl + o) =
                    (uint32_t)__bfloat16_as_ushort(l1) << 16 | __bfloat16_as_ushort(l0);
            }
        }
    }
}

// ---------------------------------------------------------------------------
// GEMM 2: scores. per batch: xp[1024,HD] x yp[1024,HD]^T + maskbias -> g_sc
// ---------------------------------------------------------------------------
__global__ __launch_bounds__(256, 1)
void mma_scores_kernel()
{
    extern __shared__ char smraw[];
    char* smp = (char*)(((uintptr_t)smraw + 1023) & ~(uintptr_t)1023);
    uint32_t sb = smem_u32(smp);
    const int tid = threadIdx.x;
    const int b = blockIdx.z;
    const int m0 = blockIdx.x * 256, n0 = blockIdx.y * 128;
    const size_t arow = (size_t)(b * L1D + m0) * HD;
    const size_t brow = (size_t)(BSZ * L1D + b * L2D + n0) * HD;

    float acc[4][8][4] = {};
    mma_gemm(g_ph + arow, g_pl + arow, HD,
             g_ph + brow, g_pl + brow, HD,
             HD / 64, sb, tid, acc);

    EPI_SETUP();
    const float* mb = g_maskbias + b * L2D;
    #pragma unroll
    for (int mi = 0; mi < 4; ++mi) {
        #pragma unroll
        for (int ni = 0; ni < 8; ++ni) {
            int n = n0 + wn * 64 + ni * 8 + ec;
            float b0 = mb[n], b1 = mb[n + 1];
            #pragma unroll
            for (int h = 0; h < 2; ++h) {
                int m = m0 + wm * 64 + mi * 16 + er + h * 8;
                float2 v = make_float2(acc[mi][ni][2 * h] + b0,
                                       acc[mi][ni][2 * h + 1] + b1);
                *(float2*)(g_sc + ((size_t)b * L1D + m) * L2D + n) = v;
            }
        }
    }
}

// ---------------------------------------------------------------------------
// softmax over last dim; writes P split to bf16 hi/lo
// ---------------------------------------------------------------------------
__global__ __launch_bounds__(256) void softmax_split_kernel()
{
    const int row = blockIdx.x;
    const float* p = g_sc + (size_t)row * L2D;
    __nv_bfloat16* ph = g_Ph + (size_t)row * L2D;
    __nv_bfloat16* pl = g_Pl + (size_t)row * L2D;
    const int t = threadIdx.x;
    __shared__ float red[8];

    float v[4];
    float mx = NEG_BIG;
    #pragma unroll
    for (int u = 0; u < 4; u++) { v[u] = p[t + u * 256]; mx = fmaxf(mx, v[u]); }
    #pragma unroll
    for (int o = 16; o > 0; o >>= 1) mx = fmaxf(mx, __shfl_xor_sync(~0u, mx, o));
    if ((t & 31) == 0) red[t >> 5] = mx;
    __syncthreads();
    if (t == 0) {
        float m = red[0];
        #pragma unroll
        for (int i = 1; i < 8; i++) m = fmaxf(m, red[i]);
        red[0] = m;
    }
    __syncthreads();
    mx = red[0];
    __syncthreads();

    float s = 0.f;
    #pragma unroll
    for (int u = 0; u < 4; u++) { v[u] = __expf(v[u] - mx); s += v[u]; }
    #pragma unroll
    for (int o = 16; o > 0; o >>= 1) s += __shfl_xor_sync(~0u, s, o);
    if ((t & 31) == 0) red[t >> 5] = s;
    __syncthreads();
    if (t == 0) {
        float m = 0.f;
        #pragma unroll
        for (int i = 0; i < 8; i++) m += red[i];
        red[0] = m;
    }
    __syncthreads();
    float inv = 1.0f / red[0];
    #pragma unroll
    for (int u = 0; u < 4; u++) {
        float pv = v[u] * inv;
        __nv_bfloat16 h, l;
        split1(pv, h, l);
        ph[t + u * 256] = h;
        pl[t + u * 256] = l;
    }
}

// ---------------------------------------------------------------------------
// GEMM 3: attn + concat. per batch: P[1024,1024] x x2t[HD,1024]^T -> att
// out[b,i] = [x1 | att | x1*att | x1-att]
// ---------------------------------------------------------------------------
__global__ __launch_bounds__(256, 1)
void mma_attn_kernel(const float* __restrict__ X1, float* __restrict__ Out)
{
    extern __shared__ char smraw[];
    char* smp = (char*)(((uintptr_t)smraw + 1023) & ~(uintptr_t)1023);
    uint32_t sb = smem_u32(smp);
    const int tid = threadIdx.x;
    const int b = blockIdx.z;
    const int m0 = blockIdx.x * 256, n0 = blockIdx.y * 128;
    const size_t arow = ((size_t)b * L1D + m0) * L2D;
    const size_t brow = ((size_t)b * HD + n0) * L2D;

    float acc[4][8][4] = {};
    mma_gemm(g_Ph + arow, g_Pl + arow, L2D,
             g_x2th + brow, g_x2tl + brow, L2D,
             L2D / 64, sb, tid, acc);

    EPI_SETUP();
    #pragma unroll
    for (int mi = 0; mi < 4; ++mi) {
        #pragma unroll
        for (int ni = 0; ni < 8; ++ni) {
            int n = n0 + wn * 64 + ni * 8 + ec;
            #pragma unroll
            for (int h = 0; h < 2; ++h) {
                int m = m0 + wm * 64 + mi * 16 + er + h * 8;
                const float* x1row = X1 + ((size_t)b * L1D + m) * HD;
                float* orow = Out + ((size_t)b * L1D + m) * (size_t)(4 * HD);
                float2 a = make_float2(acc[mi][ni][2 * h], acc[mi][ni][2 * h + 1]);
                float2 xv = *(const float2*)(x1row + n);
                *(float2*)(orow + n)          = xv;
                *(float2*)(orow + HD + n)     = a;
                *(float2*)(orow + 2 * HD + n) = make_float2(xv.x * a.x, xv.y * a.y);
                *(float2*)(orow + 3 * HD + n) = make_float2(xv.x - a.x, xv.y - a.y);
            }
        }
    }
}

// ---------------------------------------------------------------------------
extern "C" void kernel_launch(void* const* d_in, const int* in_sizes, int n_in,
                              void* d_out, int out_size)
{
    const float* x1      = (const float*)d_in[0];
    const float* x2      = (const float*)d_in[1];
    const void*  x2_mask = d_in[3];
    const float* W       = (const float*)d_in[4];
    const float* bias    = (const float*)d_in[5];
    float* out = (float*)d_out;
    (void)in_sizes; (void)n_in; (void)out_size;

    cudaFuncSetAttribute(mma_proj_kernel,   cudaFuncAttributeMaxDynamicSharedMemorySize, SMEM_GEMM);
    cudaFuncSetAttribute(mma_scores_kernel, cudaFuncAttributeMaxDynamicSharedMemorySize, SMEM_GEMM);
    cudaFuncSetAttribute(mma_attn_kernel,   cudaFuncAttributeMaxDynamicSharedMemorySize, SMEM_GEMM);

    // Launch order: index 3 = mma_scores_kernel (the ncu-captured slot).
    // 0 mask, 1 split_all, 2 proj, 3 scores, 4 transpose, 5 softmax, 6 attn
    mask_kernel<<<1, 1024>>>(x2_mask);

    int ntot4 = 2 * N4_X + N4_W;
    split_all_kernel<<<(ntot4 + 255) / 256, 256>>>(x1, x2, W);

    mma_proj_kernel<<<dim3(HD / 128, MROWS / 256), 256, SMEM_GEMM>>>(bias);

    mma_scores_kernel<<<dim3(L1D / 256, L2D / 128, BSZ), 256, SMEM_GEMM>>>();

    transpose_split_kernel<<<dim3(L2D / 32, HD / 32, BSZ), dim3(32, 8)>>>(x2);

    softmax_split_kernel<<<BSZ * L1D, 256>>>();

    mma_attn_kernel<<<dim3(L1D / 256, HD / 128, BSZ), 256, SMEM_GEMM>>>(x1, out);
}